// round 2
// baseline (speedup 1.0000x reference)
#include <cuda_runtime.h>
#include <cuda_bf16.h>

// Problem constants
#define BB   2
#define SS   2048
#define DD   1024
#define HH   16
#define DK   64
#define N3   3072   // 3*D
#define NTOK 4096   // B*S

// Scratch (allocation-free rule: __device__ globals)
__device__ float g_q[BB * HH * SS * DK];   // [bh, s, dk]
__device__ float g_k[BB * HH * SS * DK];
__device__ float g_v[BB * HH * SS * DK];
__device__ float g_o[NTOK * DD];           // [token, h*64+d]

// ---------------------------------------------------------------------------
// Kernel 1: QKV projection. C[m,n] = sum_k X[m,k] * W[n,k] + bias[n]
// Scatter epilogue into g_q/g_k/g_v with [bh, s, dk] layout.
// Tiles: BM=BN=64, BK=16, 256 threads, 4x4 microtile.
// ---------------------------------------------------------------------------
__global__ __launch_bounds__(256) void qkv_gemm_kernel(
    const float* __restrict__ X, const float* __restrict__ W,
    const float* __restrict__ bias)
{
    __shared__ __align__(16) float As[16][64];
    __shared__ __align__(16) float Bs[16][64];

    const int K = DD;
    const int t  = threadIdx.x;
    const int tx = t & 15, ty = t >> 4;
    const int m0 = blockIdx.y * 64;
    const int n0 = blockIdx.x * 64;

    const int lrow = t >> 2;        // 0..63
    const int lk4  = (t & 3) * 4;   // 0,4,8,12

    const float* Ag = X + (m0 + lrow) * K + lk4;
    const float* Bg = W + (n0 + lrow) * K + lk4;

    float acc[4][4];
#pragma unroll
    for (int i = 0; i < 4; i++)
#pragma unroll
        for (int j = 0; j < 4; j++) acc[i][j] = 0.0f;

    for (int k0 = 0; k0 < K; k0 += 16) {
        float4 a = *(const float4*)(Ag + k0);
        float4 b = *(const float4*)(Bg + k0);
        As[lk4 + 0][lrow] = a.x; As[lk4 + 1][lrow] = a.y;
        As[lk4 + 2][lrow] = a.z; As[lk4 + 3][lrow] = a.w;
        Bs[lk4 + 0][lrow] = b.x; Bs[lk4 + 1][lrow] = b.y;
        Bs[lk4 + 2][lrow] = b.z; Bs[lk4 + 3][lrow] = b.w;
        __syncthreads();
#pragma unroll
        for (int kk = 0; kk < 16; kk++) {
            float4 av = *(const float4*)&As[kk][ty * 4];
            float4 bv = *(const float4*)&Bs[kk][tx * 4];
            acc[0][0] += av.x * bv.x; acc[0][1] += av.x * bv.y;
            acc[0][2] += av.x * bv.z; acc[0][3] += av.x * bv.w;
            acc[1][0] += av.y * bv.x; acc[1][1] += av.y * bv.y;
            acc[1][2] += av.y * bv.z; acc[1][3] += av.y * bv.w;
            acc[2][0] += av.z * bv.x; acc[2][1] += av.z * bv.y;
            acc[2][2] += av.z * bv.z; acc[2][3] += av.z * bv.w;
            acc[3][0] += av.w * bv.x; acc[3][1] += av.w * bv.y;
            acc[3][2] += av.w * bv.z; acc[3][3] += av.w * bv.w;
        }
        __syncthreads();
    }

    // Epilogue: whole block maps to one (sel, head) since BN == DK == 64.
    const int sel = n0 >> 10;               // 0:Q 1:K 2:V
    const int h   = (n0 & 1023) >> 6;
    float* dst = (sel == 0) ? g_q : ((sel == 1) ? g_k : g_v);
    float4 bv = *(const float4*)&bias[n0 + tx * 4];

#pragma unroll
    for (int i = 0; i < 4; i++) {
        int m = m0 + ty * 4 + i;
        int bidx = m >> 11;                 // token / 2048
        int s    = m & 2047;
        float4 o;
        o.x = acc[i][0] + bv.x; o.y = acc[i][1] + bv.y;
        o.z = acc[i][2] + bv.z; o.w = acc[i][3] + bv.w;
        *(float4*)&dst[(((bidx * HH + h) * SS) + s) * DK + tx * 4] = o;
    }
}

// ---------------------------------------------------------------------------
// Kernel 2: fp32 flash attention, causal, BLOCK_M = BLOCK_N = 64, d = 64.
// smem: Qs (16KB) + KV union K/V (16KB) + Ps (16KB) = 48KB static exactly.
// K is XOR-swizzled at float4 granularity: phys_quad = d4 ^ (row>>2).
// ---------------------------------------------------------------------------
__global__ __launch_bounds__(256) void flash_attn_kernel()
{
    __shared__ __align__(16) float Qs[64][64];
    __shared__ __align__(16) float KV[64][64];
    __shared__ __align__(16) float Ps[64][64];

    const int t  = threadIdx.x;
    const int tx = t & 15, ty = t >> 4;
    const int bh = blockIdx.y;                       // 0..31
    const int qt = (int)gridDim.x - 1 - (int)blockIdx.x;  // heavy blocks first
    const int q0 = qt * 64;

    const float* Qg = g_q + (bh * SS + q0) * DK;
    const float* Kg = g_k + bh * SS * DK;
    const float* Vg = g_v + bh * SS * DK;

    // Load Q tile (row-major, float4 stores, conflict-free)
#pragma unroll
    for (int it = 0; it < 4; it++) {
        int idx = t + it * 256;
        int r = idx >> 4, c4 = (idx & 15) * 4;
        *(float4*)&Qs[r][c4] = *(const float4*)&Qg[r * DK + c4];
    }
    // Load K tile 0 (swizzled)
#pragma unroll
    for (int it = 0; it < 4; it++) {
        int idx = t + it * 256;
        int r = idx >> 4, dq = idx & 15;
        int pq = dq ^ (r >> 2);
        *(float4*)&KV[r][pq * 4] = *(const float4*)&Kg[r * DK + dq * 4];
    }
    __syncthreads();

    float m_st[4], l_st[4], O[4][4];
#pragma unroll
    for (int i = 0; i < 4; i++) {
        m_st[i] = -1e30f; l_st[i] = 0.0f;
#pragma unroll
        for (int j = 0; j < 4; j++) O[i][j] = 0.0f;
    }

    const int ntiles = q0 / 64 + 1;
    const float sc = 0.125f;   // 1/sqrt(64)

    for (int jt = 0; jt < ntiles; jt++) {
        const int j0 = jt * 64;

        // Prefetch V tile into registers (overlaps with S compute)
        float4 rv[4];
#pragma unroll
        for (int it = 0; it < 4; it++) {
            int idx = t + it * 256;
            int r = idx >> 4, dq = idx & 15;
            rv[it] = *(const float4*)&Vg[(j0 + r) * DK + dq * 4];
        }

        // S = Q K^T
        float s[4][4];
#pragma unroll
        for (int i = 0; i < 4; i++)
#pragma unroll
            for (int j = 0; j < 4; j++) s[i][j] = 0.0f;

#pragma unroll
        for (int d4 = 0; d4 < 16; d4++) {
            float4 q[4], k[4];
#pragma unroll
            for (int i = 0; i < 4; i++)
                q[i] = *(const float4*)&Qs[4 * ty + i][d4 * 4];
#pragma unroll
            for (int j = 0; j < 4; j++)
                k[j] = *(const float4*)&KV[4 * tx + j][(d4 ^ tx) * 4];
#pragma unroll
            for (int i = 0; i < 4; i++)
#pragma unroll
                for (int j = 0; j < 4; j++)
                    s[i][j] += q[i].x * k[j].x + q[i].y * k[j].y
                             + q[i].z * k[j].z + q[i].w * k[j].w;
        }

        const bool diag = (j0 == q0);
#pragma unroll
        for (int i = 0; i < 4; i++)
#pragma unroll
            for (int j = 0; j < 4; j++) {
                float v = s[i][j] * sc;
                if (diag && (4 * tx + j > 4 * ty + i)) v = -1e30f;
                s[i][j] = v;
            }

        // Online softmax per row (16 lanes per row: same ty, tx 0..15)
#pragma unroll
        for (int i = 0; i < 4; i++) {
            float tm = fmaxf(fmaxf(s[i][0], s[i][1]), fmaxf(s[i][2], s[i][3]));
            tm = fmaxf(tm, __shfl_xor_sync(0xffffffffu, tm, 1));
            tm = fmaxf(tm, __shfl_xor_sync(0xffffffffu, tm, 2));
            tm = fmaxf(tm, __shfl_xor_sync(0xffffffffu, tm, 4));
            tm = fmaxf(tm, __shfl_xor_sync(0xffffffffu, tm, 8));
            float mnew  = fmaxf(m_st[i], tm);
            float alpha = __expf(m_st[i] - mnew);
            float rs = 0.0f;
#pragma unroll
            for (int j = 0; j < 4; j++) {
                float p = __expf(s[i][j] - mnew);
                s[i][j] = p;
                rs += p;
            }
            rs += __shfl_xor_sync(0xffffffffu, rs, 1);
            rs += __shfl_xor_sync(0xffffffffu, rs, 2);
            rs += __shfl_xor_sync(0xffffffffu, rs, 4);
            rs += __shfl_xor_sync(0xffffffffu, rs, 8);
            l_st[i] = l_st[i] * alpha + rs;
            m_st[i] = mnew;
#pragma unroll
            for (int j = 0; j < 4; j++) O[i][j] *= alpha;
        }

        // Store P tile
#pragma unroll
        for (int i = 0; i < 4; i++) {
            float4 p4; p4.x = s[i][0]; p4.y = s[i][1]; p4.z = s[i][2]; p4.w = s[i][3];
            *(float4*)&Ps[4 * ty + i][4 * tx] = p4;
        }
        __syncthreads();   // S-phase KV(K) reads + Ps writes complete

        // KV <- V (from registers)
#pragma unroll
        for (int it = 0; it < 4; it++) {
            int idx = t + it * 256;
            int r = idx >> 4, dq = idx & 15;
            *(float4*)&KV[r][dq * 4] = rv[it];
        }
        __syncthreads();

        // Prefetch next K into registers (overlaps with PV compute)
        float4 rk[4];
        if (jt + 1 < ntiles) {
#pragma unroll
            for (int it = 0; it < 4; it++) {
                int idx = t + it * 256;
                int r = idx >> 4, dq = idx & 15;
                rk[it] = *(const float4*)&Kg[(j0 + 64 + r) * DK + dq * 4];
            }
        }

        // O += P V
#pragma unroll
        for (int n4 = 0; n4 < 16; n4++) {
            float4 p[4], v[4];
#pragma unroll
            for (int i = 0; i < 4; i++)
                p[i] = *(const float4*)&Ps[4 * ty + i][n4 * 4];
#pragma unroll
            for (int c = 0; c < 4; c++)
                v[c] = *(const float4*)&KV[n4 * 4 + c][4 * tx];
#pragma unroll
            for (int i = 0; i < 4; i++) {
                O[i][0] += p[i].x * v[0].x + p[i].y * v[1].x + p[i].z * v[2].x + p[i].w * v[3].x;
                O[i][1] += p[i].x * v[0].y + p[i].y * v[1].y + p[i].z * v[2].y + p[i].w * v[3].y;
                O[i][2] += p[i].x * v[0].z + p[i].y * v[1].z + p[i].z * v[2].z + p[i].w * v[3].z;
                O[i][3] += p[i].x * v[0].w + p[i].y * v[1].w + p[i].z * v[2].w + p[i].w * v[3].w;
            }
        }
        __syncthreads();   // PV reads done before KV overwrite

        if (jt + 1 < ntiles) {
#pragma unroll
            for (int it = 0; it < 4; it++) {
                int idx = t + it * 256;
                int r = idx >> 4, dq = idx & 15;
                int pq = dq ^ (r >> 2);
                *(float4*)&KV[r][pq * 4] = rk[it];
            }
        }
        __syncthreads();
    }

    // Normalize and write O tile: g_o[token][h*64 + d]
    const int b = bh >> 4, h = bh & 15;
#pragma unroll
    for (int i = 0; i < 4; i++) {
        float inv = 1.0f / l_st[i];
        int qg = q0 + 4 * ty + i;
        float4 o;
        o.x = O[i][0] * inv; o.y = O[i][1] * inv;
        o.z = O[i][2] * inv; o.w = O[i][3] * inv;
        *(float4*)&g_o[(b * SS + qg) * DD + h * 64 + 4 * tx] = o;
    }
}

// ---------------------------------------------------------------------------
// Kernel 3: output projection. out[m,n] = sum_k g_o[m,k] * Wo[n,k] + bo[n]
// ---------------------------------------------------------------------------
__global__ __launch_bounds__(256) void oproj_gemm_kernel(
    const float* __restrict__ W, const float* __restrict__ bias,
    float* __restrict__ out)
{
    __shared__ __align__(16) float As[16][64];
    __shared__ __align__(16) float Bs[16][64];

    const int K = DD;
    const int t  = threadIdx.x;
    const int tx = t & 15, ty = t >> 4;
    const int m0 = blockIdx.y * 64;
    const int n0 = blockIdx.x * 64;

    const int lrow = t >> 2;
    const int lk4  = (t & 3) * 4;

    const float* Ag = g_o + (m0 + lrow) * K + lk4;
    const float* Bg = W + (n0 + lrow) * K + lk4;

    float acc[4][4];
#pragma unroll
    for (int i = 0; i < 4; i++)
#pragma unroll
        for (int j = 0; j < 4; j++) acc[i][j] = 0.0f;

    for (int k0 = 0; k0 < K; k0 += 16) {
        float4 a = *(const float4*)(Ag + k0);
        float4 b = *(const float4*)(Bg + k0);
        As[lk4 + 0][lrow] = a.x; As[lk4 + 1][lrow] = a.y;
        As[lk4 + 2][lrow] = a.z; As[lk4 + 3][lrow] = a.w;
        Bs[lk4 + 0][lrow] = b.x; Bs[lk4 + 1][lrow] = b.y;
        Bs[lk4 + 2][lrow] = b.z; Bs[lk4 + 3][lrow] = b.w;
        __syncthreads();
#pragma unroll
        for (int kk = 0; kk < 16; kk++) {
            float4 av = *(const float4*)&As[kk][ty * 4];
            float4 bv = *(const float4*)&Bs[kk][tx * 4];
            acc[0][0] += av.x * bv.x; acc[0][1] += av.x * bv.y;
            acc[0][2] += av.x * bv.z; acc[0][3] += av.x * bv.w;
            acc[1][0] += av.y * bv.x; acc[1][1] += av.y * bv.y;
            acc[1][2] += av.y * bv.z; acc[1][3] += av.y * bv.w;
            acc[2][0] += av.z * bv.x; acc[2][1] += av.z * bv.y;
            acc[2][2] += av.z * bv.z; acc[2][3] += av.z * bv.w;
            acc[3][0] += av.w * bv.x; acc[3][1] += av.w * bv.y;
            acc[3][2] += av.w * bv.z; acc[3][3] += av.w * bv.w;
        }
        __syncthreads();
    }

    float4 bv = *(const float4*)&bias[n0 + tx * 4];
#pragma unroll
    for (int i = 0; i < 4; i++) {
        int m = m0 + ty * 4 + i;
        float4 o;
        o.x = acc[i][0] + bv.x; o.y = acc[i][1] + bv.y;
        o.z = acc[i][2] + bv.z; o.w = acc[i][3] + bv.w;
        *(float4*)&out[m * DD + n0 + tx * 4] = o;
    }
}

// ---------------------------------------------------------------------------
extern "C" void kernel_launch(void* const* d_in, const int* in_sizes, int n_in,
                              void* d_out, int out_size)
{
    const float* x      = (const float*)d_in[0];
    // d_in[1] = mask (causal tril; structure exploited directly)
    const float* w_qkv  = (const float*)d_in[2];
    const float* b_qkv  = (const float*)d_in[3];
    const float* w_o    = (const float*)d_in[4];
    const float* b_o    = (const float*)d_in[5];
    float* out          = (float*)d_out;

    (void)in_sizes; (void)n_in; (void)out_size;

    dim3 g1(N3 / 64, NTOK / 64);       // 48 x 64
    qkv_gemm_kernel<<<g1, 256>>>(x, w_qkv, b_qkv);

    dim3 g2(SS / 64, BB * HH);         // 32 x 32
    flash_attn_kernel<<<g2, 256>>>();

    dim3 g3(DD / 64, NTOK / 64);       // 16 x 64
    oproj_gemm_kernel<<<g3, 256>>>(w_o, b_o, out);
}

// round 5
// speedup vs baseline: 2.0879x; 2.0879x over previous
#include <cuda_runtime.h>
#include <cuda_bf16.h>
#include <cstdint>

// Problem constants
#define BB   2
#define SS   2048
#define DD   1024
#define HH   16
#define DK   64
#define N3   3072   // 3*D
#define NTOK 4096   // B*S

// Scratch (allocation-free rule: __device__ globals)
__device__ float g_q[BB * HH * SS * DK];   // [bh, s, dk]
__device__ float g_k[BB * HH * SS * DK];
__device__ float g_v[BB * HH * SS * DK];
__device__ float g_o[NTOK * DD];           // [token, h*64+d]

// ---------------------------------------------------------------------------
// PTX helpers — base sm_80+ ISA only (harness targets plain sm_103: NO tcgen05)
// ---------------------------------------------------------------------------
__device__ __forceinline__ uint32_t smem_u32(const void* p) {
    uint32_t a;
    asm("{ .reg .u64 t; cvta.to.shared.u64 t, %1; cvt.u32.u64 %0, t; }"
        : "=r"(a) : "l"(p));
    return a;
}

#define CP16(dst, src) \
    asm volatile("cp.async.cg.shared.global [%0], [%1], 16;" :: "r"(dst), "l"(src))
#define CP_COMMIT() asm volatile("cp.async.commit_group;" ::: "memory")
#define CP_WAIT(n)  asm volatile("cp.async.wait_group %0;" :: "n"(n) : "memory")

__device__ __forceinline__ void ldsm4(uint32_t* r, uint32_t addr) {
    asm volatile("ldmatrix.sync.aligned.m8n8.x4.shared.b16 {%0,%1,%2,%3}, [%4];"
        : "=r"(r[0]), "=r"(r[1]), "=r"(r[2]), "=r"(r[3]) : "r"(addr));
}

// f32 -> tf32 round-to-nearest (critical: truncation bias would exceed 1e-3)
__device__ __forceinline__ uint32_t f2tf(uint32_t x) {
    uint32_t r;
    asm("cvt.rna.tf32.f32 %0, %1;" : "=r"(r) : "f"(__uint_as_float(x)));
    return r;
}

__device__ __forceinline__ void mma_tf32(float* c, const uint32_t* a,
                                         uint32_t b0, uint32_t b1) {
    asm volatile(
        "mma.sync.aligned.m16n8k8.row.col.f32.tf32.tf32.f32 "
        "{%0,%1,%2,%3}, {%4,%5,%6,%7}, {%8,%9}, {%0,%1,%2,%3};"
        : "+f"(c[0]), "+f"(c[1]), "+f"(c[2]), "+f"(c[3])
        : "r"(a[0]), "r"(a[1]), "r"(a[2]), "r"(a[3]), "r"(b0), "r"(b1));
}

// ---------------------------------------------------------------------------
// tf32 mma.sync GEMM: C[m,n] = sum_k A[m,k]*W[n,k] + bias[n]
// MODE 0: A = X, scatter epilogue into g_q/g_k/g_v   (QKV projection)
// MODE 1: A = g_o, epilogue writes Out row-major     (output projection)
// Block tile 128x128, 8 warps (warp tile 64x32), K chunks of 32 (128B rows,
// XOR-16B swizzle), 3-stage cp.async pipeline.
// ---------------------------------------------------------------------------
#define STAGES      3
#define STAGE_BYTES 32768           // A tile 16KB + B tile 16KB
#define NCHUNK      32              // K=1024 / 32
#define GEMM_SMEM   (1024 + STAGES * STAGE_BYTES)

template<int MODE>
__global__ __launch_bounds__(256, 2) void gemm_mma(
    const float* __restrict__ Ain, const float* __restrict__ Bw,
    const float* __restrict__ bias, float* __restrict__ Out)
{
    extern __shared__ __align__(16) char smem_raw[];
    const uint32_t sb  = smem_u32(smem_raw);
    const uint32_t st0 = (sb + 1023u) & ~1023u;   // stage buffers, 1KB aligned

    const int t    = threadIdx.x;
    const int lane = t & 31;
    const int wid  = t >> 5;
    const int wm   = wid & 1;          // warp m index (2)
    const int wn   = wid >> 1;         // warp n index (4)
    const int m0   = blockIdx.y * 128;
    const int n0   = blockIdx.x * 128;

    const float* A = (MODE == 1) ? g_o : Ain;

    // ---- cp.async load geometry: 8 x 16B per thread per chunk -------------
    const int rb = t >> 3;            // base row 0..31
    const int q  = t & 7;             // 16B quad within 128B row
    const float* Abase = A  + (size_t)m0 * DD + q * 4;
    const float* Bbase = Bw + (size_t)n0 * DD + q * 4;

    auto load_chunk = [&](int c) {
        const uint32_t st = st0 + (c % STAGES) * STAGE_BYTES;
        const float* Ac = Abase + c * 32;
        const float* Bc = Bbase + c * 32;
#pragma unroll
        for (int it = 0; it < 4; it++) {
            int r = rb + it * 32;
            CP16(st + r * 128 + ((q ^ (r & 7)) << 4), Ac + (size_t)r * DD);
        }
#pragma unroll
        for (int it = 0; it < 4; it++) {
            int r = rb + it * 32;
            CP16(st + 16384 + r * 128 + ((q ^ (r & 7)) << 4), Bc + (size_t)r * DD);
        }
    };

    // ---- ldmatrix fragment geometry ---------------------------------------
    // A (x4): lanes 0-7 m-rows 0-7 q0 | 8-15 rows 8-15 q0 | 16-23 rows 0-7 q1
    //         | 24-31 rows 8-15 q1  => regs = {a0,a1,a2,a3} of m16n8k8
    const int rx   = lane & 7;
    const int aq   = (lane >> 4) & 1;
    const int arow = ((lane >> 3) & 1) * 8 + rx;
    uint32_t arow_off[4];
#pragma unroll
    for (int mt = 0; mt < 4; mt++)
        arow_off[mt] = (wm * 64 + mt * 16 + arow) * 128;
    // B (x4): lanes 0-7 n-rows 0-7 q0 | 8-15 rows 0-7 q1 | 16-23 rows 8-15 q0
    //         | 24-31 rows 8-15 q1 => regs = {b0,b1} of two n-tiles
    const int bq   = (lane >> 3) & 1;
    const int brow = ((lane >> 4) & 1) * 8 + rx;
    uint32_t brow_off[2];
#pragma unroll
    for (int np = 0; np < 2; np++)
        brow_off[np] = (wn * 32 + np * 16 + brow) * 128;

    float acc[4][4][4];
#pragma unroll
    for (int mt = 0; mt < 4; mt++)
#pragma unroll
        for (int nt = 0; nt < 4; nt++)
#pragma unroll
            for (int i = 0; i < 4; i++) acc[mt][nt][i] = 0.0f;

    // prologue: chunks 0,1 in flight
    load_chunk(0); CP_COMMIT();
    load_chunk(1); CP_COMMIT();

    for (int c = 0; c < NCHUNK; c++) {
        CP_WAIT(1);
        __syncthreads();     // chunk c visible; stage (c+2)%3 fully consumed

        if (c + 2 < NCHUNK) load_chunk(c + 2);
        CP_COMMIT();         // empty group ok at tail -> uniform accounting

        const uint32_t stA = st0 + (c % STAGES) * STAGE_BYTES;
        const uint32_t stB = stA + 16384;
#pragma unroll
        for (int ks = 0; ks < 4; ks++) {
            uint32_t a[4][4], b[2][4];
#pragma unroll
            for (int mt = 0; mt < 4; mt++)
                ldsm4(a[mt], stA + arow_off[mt] + (((ks * 2 + aq) ^ rx) << 4));
#pragma unroll
            for (int np = 0; np < 2; np++)
                ldsm4(b[np], stB + brow_off[np] + (((ks * 2 + bq) ^ rx) << 4));
#pragma unroll
            for (int mt = 0; mt < 4; mt++)
#pragma unroll
                for (int i = 0; i < 4; i++) a[mt][i] = f2tf(a[mt][i]);
#pragma unroll
            for (int np = 0; np < 2; np++)
#pragma unroll
                for (int i = 0; i < 4; i++) b[np][i] = f2tf(b[np][i]);
#pragma unroll
            for (int mt = 0; mt < 4; mt++)
#pragma unroll
                for (int nt = 0; nt < 4; nt++)
                    mma_tf32(acc[mt][nt],
                             a[mt],
                             b[nt >> 1][(nt & 1) * 2],
                             b[nt >> 1][(nt & 1) * 2 + 1]);
        }
    }

    // ---- epilogue ----------------------------------------------------------
    // c-frag: c0 (row g, col 2*t4), c1 (col+1), c2/c3 (row g+8)
    const int g  = lane >> 2;
    const int t4 = lane & 3;
#pragma unroll
    for (int mt = 0; mt < 4; mt++) {
        const int m = m0 + wm * 64 + mt * 16 + g;
#pragma unroll
        for (int nt = 0; nt < 4; nt++) {
            const int n = n0 + wn * 32 + nt * 8 + 2 * t4;
            const float2 b2 = *(const float2*)&bias[n];
            float2 v0, v1;
            v0.x = acc[mt][nt][0] + b2.x; v0.y = acc[mt][nt][1] + b2.y;
            v1.x = acc[mt][nt][2] + b2.x; v1.y = acc[mt][nt][3] + b2.y;
            if (MODE == 1) {
                *(float2*)&Out[(size_t)m * DD + n]       = v0;
                *(float2*)&Out[(size_t)(m + 8) * DD + n] = v1;
            } else {
                const int sel = n >> 10;                // 0:Q 1:K 2:V
                const int h   = (n & 1023) >> 6;
                const int dk  = n & 63;
                float* dst = (sel == 0) ? g_q : ((sel == 1) ? g_k : g_v);
                const int b0i = m >> 11, s0 = m & 2047;
                *(float2*)&dst[((size_t)(b0i * HH + h) * SS + s0) * DK + dk] = v0;
                const int b1i = (m + 8) >> 11, s1 = (m + 8) & 2047;
                *(float2*)&dst[((size_t)(b1i * HH + h) * SS + s1) * DK + dk] = v1;
            }
        }
    }
}

// ---------------------------------------------------------------------------
// Kernel 2: fp32 flash attention, causal, BLOCK_M = BLOCK_N = 64, d = 64.
// (unchanged from the passing round-1 kernel)
// ---------------------------------------------------------------------------
__global__ __launch_bounds__(256) void flash_attn_kernel()
{
    __shared__ __align__(16) float Qs[64][64];
    __shared__ __align__(16) float KV[64][64];
    __shared__ __align__(16) float Ps[64][64];

    const int t  = threadIdx.x;
    const int tx = t & 15, ty = t >> 4;
    const int bh = blockIdx.y;
    const int qt = (int)gridDim.x - 1 - (int)blockIdx.x;
    const int q0 = qt * 64;

    const float* Qg = g_q + (bh * SS + q0) * DK;
    const float* Kg = g_k + bh * SS * DK;
    const float* Vg = g_v + bh * SS * DK;

#pragma unroll
    for (int it = 0; it < 4; it++) {
        int idx = t + it * 256;
        int r = idx >> 4, c4 = (idx & 15) * 4;
        *(float4*)&Qs[r][c4] = *(const float4*)&Qg[r * DK + c4];
    }
#pragma unroll
    for (int it = 0; it < 4; it++) {
        int idx = t + it * 256;
        int r = idx >> 4, dq = idx & 15;
        int pq = dq ^ (r >> 2);
        *(float4*)&KV[r][pq * 4] = *(const float4*)&Kg[r * DK + dq * 4];
    }
    __syncthreads();

    float m_st[4], l_st[4], O[4][4];
#pragma unroll
    for (int i = 0; i < 4; i++) {
        m_st[i] = -1e30f; l_st[i] = 0.0f;
#pragma unroll
        for (int j = 0; j < 4; j++) O[i][j] = 0.0f;
    }

    const int ntiles = q0 / 64 + 1;
    const float sc = 0.125f;

    for (int jt = 0; jt < ntiles; jt++) {
        const int j0 = jt * 64;

        float4 rv[4];
#pragma unroll
        for (int it = 0; it < 4; it++) {
            int idx = t + it * 256;
            int r = idx >> 4, dq = idx & 15;
            rv[it] = *(const float4*)&Vg[(j0 + r) * DK + dq * 4];
        }

        float s[4][4];
#pragma unroll
        for (int i = 0; i < 4; i++)
#pragma unroll
            for (int j = 0; j < 4; j++) s[i][j] = 0.0f;

#pragma unroll
        for (int d4 = 0; d4 < 16; d4++) {
            float4 qv[4], kv[4];
#pragma unroll
            for (int i = 0; i < 4; i++)
                qv[i] = *(const float4*)&Qs[4 * ty + i][d4 * 4];
#pragma unroll
            for (int j = 0; j < 4; j++)
                kv[j] = *(const float4*)&KV[4 * tx + j][(d4 ^ tx) * 4];
#pragma unroll
            for (int i = 0; i < 4; i++)
#pragma unroll
                for (int j = 0; j < 4; j++)
                    s[i][j] += qv[i].x * kv[j].x + qv[i].y * kv[j].y
                             + qv[i].z * kv[j].z + qv[i].w * kv[j].w;
        }

        const bool diag = (j0 == q0);
#pragma unroll
        for (int i = 0; i < 4; i++)
#pragma unroll
            for (int j = 0; j < 4; j++) {
                float v = s[i][j] * sc;
                if (diag && (4 * tx + j > 4 * ty + i)) v = -1e30f;
                s[i][j] = v;
            }

#pragma unroll
        for (int i = 0; i < 4; i++) {
            float tm = fmaxf(fmaxf(s[i][0], s[i][1]), fmaxf(s[i][2], s[i][3]));
            tm = fmaxf(tm, __shfl_xor_sync(0xffffffffu, tm, 1));
            tm = fmaxf(tm, __shfl_xor_sync(0xffffffffu, tm, 2));
            tm = fmaxf(tm, __shfl_xor_sync(0xffffffffu, tm, 4));
            tm = fmaxf(tm, __shfl_xor_sync(0xffffffffu, tm, 8));
            float mnew  = fmaxf(m_st[i], tm);
            float alpha = __expf(m_st[i] - mnew);
            float rs = 0.0f;
#pragma unroll
            for (int j = 0; j < 4; j++) {
                float p = __expf(s[i][j] - mnew);
                s[i][j] = p;
                rs += p;
            }
            rs += __shfl_xor_sync(0xffffffffu, rs, 1);
            rs += __shfl_xor_sync(0xffffffffu, rs, 2);
            rs += __shfl_xor_sync(0xffffffffu, rs, 4);
            rs += __shfl_xor_sync(0xffffffffu, rs, 8);
            l_st[i] = l_st[i] * alpha + rs;
            m_st[i] = mnew;
#pragma unroll
            for (int j = 0; j < 4; j++) O[i][j] *= alpha;
        }

#pragma unroll
        for (int i = 0; i < 4; i++) {
            float4 p4; p4.x = s[i][0]; p4.y = s[i][1]; p4.z = s[i][2]; p4.w = s[i][3];
            *(float4*)&Ps[4 * ty + i][4 * tx] = p4;
        }
        __syncthreads();

#pragma unroll
        for (int it = 0; it < 4; it++) {
            int idx = t + it * 256;
            int r = idx >> 4, dq = idx & 15;
            *(float4*)&KV[r][dq * 4] = rv[it];
        }
        __syncthreads();

        float4 rk[4];
        if (jt + 1 < ntiles) {
#pragma unroll
            for (int it = 0; it < 4; it++) {
                int idx = t + it * 256;
                int r = idx >> 4, dq = idx & 15;
                rk[it] = *(const float4*)&Kg[(j0 + 64 + r) * DK + dq * 4];
            }
        }

#pragma unroll
        for (int n4 = 0; n4 < 16; n4++) {
            float4 p[4], v[4];
#pragma unroll
            for (int i = 0; i < 4; i++)
                p[i] = *(const float4*)&Ps[4 * ty + i][n4 * 4];
#pragma unroll
            for (int c = 0; c < 4; c++)
                v[c] = *(const float4*)&KV[n4 * 4 + c][4 * tx];
#pragma unroll
            for (int i = 0; i < 4; i++) {
                O[i][0] += p[i].x * v[0].x + p[i].y * v[1].x + p[i].z * v[2].x + p[i].w * v[3].x;
                O[i][1] += p[i].x * v[0].y + p[i].y * v[1].y + p[i].z * v[2].y + p[i].w * v[3].y;
                O[i][2] += p[i].x * v[0].z + p[i].y * v[1].z + p[i].z * v[2].z + p[i].w * v[3].z;
                O[i][3] += p[i].x * v[0].w + p[i].y * v[1].w + p[i].z * v[2].w + p[i].w * v[3].w;
            }
        }
        __syncthreads();

        if (jt + 1 < ntiles) {
#pragma unroll
            for (int it = 0; it < 4; it++) {
                int idx = t + it * 256;
                int r = idx >> 4, dq = idx & 15;
                int pq = dq ^ (r >> 2);
                *(float4*)&KV[r][pq * 4] = rk[it];
            }
        }
        __syncthreads();
    }

    const int b = bh >> 4, h = bh & 15;
#pragma unroll
    for (int i = 0; i < 4; i++) {
        float inv = 1.0f / l_st[i];
        int qg = q0 + 4 * ty + i;
        float4 o;
        o.x = O[i][0] * inv; o.y = O[i][1] * inv;
        o.z = O[i][2] * inv; o.w = O[i][3] * inv;
        *(float4*)&g_o[(b * SS + qg) * DD + h * 64 + 4 * tx] = o;
    }
}

// ---------------------------------------------------------------------------
extern "C" void kernel_launch(void* const* d_in, const int* in_sizes, int n_in,
                              void* d_out, int out_size)
{
    const float* x      = (const float*)d_in[0];
    // d_in[1] = mask (causal tril; structure exploited directly)
    const float* w_qkv  = (const float*)d_in[2];
    const float* b_qkv  = (const float*)d_in[3];
    const float* w_o    = (const float*)d_in[4];
    const float* b_o    = (const float*)d_in[5];
    float* out          = (float*)d_out;

    (void)in_sizes; (void)n_in; (void)out_size;

    cudaFuncSetAttribute(gemm_mma<0>, cudaFuncAttributeMaxDynamicSharedMemorySize, GEMM_SMEM);
    cudaFuncSetAttribute(gemm_mma<1>, cudaFuncAttributeMaxDynamicSharedMemorySize, GEMM_SMEM);

    dim3 g1(N3 / 128, NTOK / 128);       // 24 x 32
    gemm_mma<0><<<g1, 256, GEMM_SMEM>>>(x, w_qkv, b_qkv, nullptr);

    dim3 g2(SS / 64, BB * HH);           // 32 x 32
    flash_attn_kernel<<<g2, 256>>>();

    dim3 g3(DD / 128, NTOK / 128);       // 8 x 32
    gemm_mma<1><<<g3, 256, GEMM_SMEM>>>(nullptr, w_o, b_o, out);
}

// round 6
// speedup vs baseline: 3.5168x; 1.6844x over previous
#include <cuda_runtime.h>
#include <cuda_bf16.h>
#include <cstdint>

// Problem constants
#define BB   2
#define SS   2048
#define DD   1024
#define HH   16
#define DK   64
#define N3   3072   // 3*D
#define NTOK 4096   // B*S

// Scratch (allocation-free rule: __device__ globals)
__device__ float g_q[BB * HH * SS * DK];   // [bh, s, dk]
__device__ float g_k[BB * HH * SS * DK];
__device__ float g_v[BB * HH * SS * DK];
__device__ float g_o[NTOK * DD];           // [token, h*64+d]

// ---------------------------------------------------------------------------
// PTX helpers — base sm_80+ ISA only (harness targets plain sm_103: NO tcgen05)
// ---------------------------------------------------------------------------
__device__ __forceinline__ uint32_t smem_u32(const void* p) {
    uint32_t a;
    asm("{ .reg .u64 t; cvta.to.shared.u64 t, %1; cvt.u32.u64 %0, t; }"
        : "=r"(a) : "l"(p));
    return a;
}

#define CP16(dst, src) \
    asm volatile("cp.async.cg.shared.global [%0], [%1], 16;" :: "r"(dst), "l"(src))
#define CP_COMMIT() asm volatile("cp.async.commit_group;" ::: "memory")
#define CP_WAIT(n)  asm volatile("cp.async.wait_group %0;" :: "n"(n) : "memory")

__device__ __forceinline__ void ldsm4(uint32_t* r, uint32_t addr) {
    asm volatile("ldmatrix.sync.aligned.m8n8.x4.shared.b16 {%0,%1,%2,%3}, [%4];"
        : "=r"(r[0]), "=r"(r[1]), "=r"(r[2]), "=r"(r[3]) : "r"(addr));
}

// f32 -> tf32 round-to-nearest (critical: truncation bias would exceed 1e-3)
__device__ __forceinline__ uint32_t f2tf(uint32_t x) {
    uint32_t r;
    asm("cvt.rna.tf32.f32 %0, %1;" : "=r"(r) : "f"(__uint_as_float(x)));
    return r;
}
__device__ __forceinline__ uint32_t f2tf_f(float x) {
    uint32_t r;
    asm("cvt.rna.tf32.f32 %0, %1;" : "=r"(r) : "f"(x));
    return r;
}

__device__ __forceinline__ void mma_tf32(float* c, const uint32_t* a,
                                         uint32_t b0, uint32_t b1) {
    asm volatile(
        "mma.sync.aligned.m16n8k8.row.col.f32.tf32.tf32.f32 "
        "{%0,%1,%2,%3}, {%4,%5,%6,%7}, {%8,%9}, {%0,%1,%2,%3};"
        : "+f"(c[0]), "+f"(c[1]), "+f"(c[2]), "+f"(c[3])
        : "r"(a[0]), "r"(a[1]), "r"(a[2]), "r"(a[3]), "r"(b0), "r"(b1));
}

// ---------------------------------------------------------------------------
// tf32 mma.sync GEMM (unchanged from the passing round-5 kernel)
// ---------------------------------------------------------------------------
#define STAGES      3
#define STAGE_BYTES 32768           // A tile 16KB + B tile 16KB
#define NCHUNK      32              // K=1024 / 32
#define GEMM_SMEM   (1024 + STAGES * STAGE_BYTES)

template<int MODE>
__global__ __launch_bounds__(256, 2) void gemm_mma(
    const float* __restrict__ Ain, const float* __restrict__ Bw,
    const float* __restrict__ bias, float* __restrict__ Out)
{
    extern __shared__ __align__(16) char smem_raw[];
    const uint32_t sb  = smem_u32(smem_raw);
    const uint32_t st0 = (sb + 1023u) & ~1023u;

    const int t    = threadIdx.x;
    const int lane = t & 31;
    const int wid  = t >> 5;
    const int wm   = wid & 1;
    const int wn   = wid >> 1;
    const int m0   = blockIdx.y * 128;
    const int n0   = blockIdx.x * 128;

    const float* A = (MODE == 1) ? g_o : Ain;

    const int rb = t >> 3;
    const int q  = t & 7;
    const float* Abase = A  + (size_t)m0 * DD + q * 4;
    const float* Bbase = Bw + (size_t)n0 * DD + q * 4;

    auto load_chunk = [&](int c) {
        const uint32_t st = st0 + (c % STAGES) * STAGE_BYTES;
        const float* Ac = Abase + c * 32;
        const float* Bc = Bbase + c * 32;
#pragma unroll
        for (int it = 0; it < 4; it++) {
            int r = rb + it * 32;
            CP16(st + r * 128 + ((q ^ (r & 7)) << 4), Ac + (size_t)r * DD);
        }
#pragma unroll
        for (int it = 0; it < 4; it++) {
            int r = rb + it * 32;
            CP16(st + 16384 + r * 128 + ((q ^ (r & 7)) << 4), Bc + (size_t)r * DD);
        }
    };

    const int rx   = lane & 7;
    const int aq   = (lane >> 4) & 1;
    const int arow = ((lane >> 3) & 1) * 8 + rx;
    uint32_t arow_off[4];
#pragma unroll
    for (int mt = 0; mt < 4; mt++)
        arow_off[mt] = (wm * 64 + mt * 16 + arow) * 128;
    const int bq   = (lane >> 3) & 1;
    const int brow = ((lane >> 4) & 1) * 8 + rx;
    uint32_t brow_off[2];
#pragma unroll
    for (int np = 0; np < 2; np++)
        brow_off[np] = (wn * 32 + np * 16 + brow) * 128;

    float acc[4][4][4];
#pragma unroll
    for (int mt = 0; mt < 4; mt++)
#pragma unroll
        for (int nt = 0; nt < 4; nt++)
#pragma unroll
            for (int i = 0; i < 4; i++) acc[mt][nt][i] = 0.0f;

    load_chunk(0); CP_COMMIT();
    load_chunk(1); CP_COMMIT();

    for (int c = 0; c < NCHUNK; c++) {
        CP_WAIT(1);
        __syncthreads();

        if (c + 2 < NCHUNK) load_chunk(c + 2);
        CP_COMMIT();

        const uint32_t stA = st0 + (c % STAGES) * STAGE_BYTES;
        const uint32_t stB = stA + 16384;
#pragma unroll
        for (int ks = 0; ks < 4; ks++) {
            uint32_t a[4][4], b[2][4];
#pragma unroll
            for (int mt = 0; mt < 4; mt++)
                ldsm4(a[mt], stA + arow_off[mt] + (((ks * 2 + aq) ^ rx) << 4));
#pragma unroll
            for (int np = 0; np < 2; np++)
                ldsm4(b[np], stB + brow_off[np] + (((ks * 2 + bq) ^ rx) << 4));
#pragma unroll
            for (int mt = 0; mt < 4; mt++)
#pragma unroll
                for (int i = 0; i < 4; i++) a[mt][i] = f2tf(a[mt][i]);
#pragma unroll
            for (int np = 0; np < 2; np++)
#pragma unroll
                for (int i = 0; i < 4; i++) b[np][i] = f2tf(b[np][i]);
#pragma unroll
            for (int mt = 0; mt < 4; mt++)
#pragma unroll
                for (int nt = 0; nt < 4; nt++)
                    mma_tf32(acc[mt][nt],
                             a[mt],
                             b[nt >> 1][(nt & 1) * 2],
                             b[nt >> 1][(nt & 1) * 2 + 1]);
        }
    }

    const int g  = lane >> 2;
    const int t4 = lane & 3;
#pragma unroll
    for (int mt = 0; mt < 4; mt++) {
        const int m = m0 + wm * 64 + mt * 16 + g;
#pragma unroll
        for (int nt = 0; nt < 4; nt++) {
            const int n = n0 + wn * 32 + nt * 8 + 2 * t4;
            const float2 b2 = *(const float2*)&bias[n];
            float2 v0, v1;
            v0.x = acc[mt][nt][0] + b2.x; v0.y = acc[mt][nt][1] + b2.y;
            v1.x = acc[mt][nt][2] + b2.x; v1.y = acc[mt][nt][3] + b2.y;
            if (MODE == 1) {
                *(float2*)&Out[(size_t)m * DD + n]       = v0;
                *(float2*)&Out[(size_t)(m + 8) * DD + n] = v1;
            } else {
                const int sel = n >> 10;
                const int h   = (n & 1023) >> 6;
                const int dk  = n & 63;
                float* dst = (sel == 0) ? g_q : ((sel == 1) ? g_k : g_v);
                const int b0i = m >> 11, s0 = m & 2047;
                *(float2*)&dst[((size_t)(b0i * HH + h) * SS + s0) * DK + dk] = v0;
                const int b1i = (m + 8) >> 11, s1 = (m + 8) & 2047;
                *(float2*)&dst[((size_t)(b1i * HH + h) * SS + s1) * DK + dk] = v1;
            }
        }
    }
}

// ---------------------------------------------------------------------------
// Kernel 2: flash attention on tf32 mma.sync.
// BLOCK_M=128, BLOCK_N=64, 8 warps (16 q-rows each), d = 64.
// Q held as tf32 a-frags in registers; K double-buffered cp.async (swizzled,
// ldmatrix b-frags); P round-trips through the dead Q smem slice (per-warp
// private rows -> __syncwarp only); V row-major with 72-float padded rows
// (conflict-free LDS b-frags).
// ---------------------------------------------------------------------------
#define FBM 128
#define FBN 64
#define QS_OFF  0                       // 128 rows x 256B (Q, then P)
#define KS_OFF  32768                   // 2 stages x 64 x 256B
#define VS_OFF  (32768 + 32768)         // 2 stages x 64 x 288B
#define FLASH_SMEM (VS_OFF + 2 * 18432) // 102400

__global__ __launch_bounds__(256) void flash_mma_kernel()
{
    extern __shared__ __align__(16) char sm[];
    const uint32_t S0 = smem_u32(sm);

    const int t    = threadIdx.x;
    const int lane = t & 31;
    const int w    = t >> 5;
    const int bh   = blockIdx.y;
    const int qt   = (int)gridDim.x - 1 - (int)blockIdx.x;   // heavy first
    const int q0   = qt * FBM;

    const float* Qg = g_q + (size_t)(bh * SS + q0) * DK;
    const float* Kg = g_k + (size_t)bh * SS * DK;
    const float* Vg = g_v + (size_t)bh * SS * DK;

    const int ntiles = q0 / FBN + 2;

    // ---- Q tile -> smem (swizzled 256B rows) ------------------------------
    {
        int r = t >> 1, h8 = (t & 1) * 8;
#pragma unroll
        for (int i = 0; i < 8; i++) {
            int qq = h8 + i;
            int ph = (qq & 8) | ((qq ^ (r & 7)) & 7);
            CP16(S0 + QS_OFF + r * 256 + ph * 16, Qg + r * 64 + qq * 4);
        }
    }
    auto load_kv = [&](int jt) {
        uint32_t stK = S0 + KS_OFF + (jt & 1) * 16384;
        uint32_t stV = S0 + VS_OFF + (jt & 1) * 18432;
        int r = t >> 2, qb = (t & 3) * 4;
        const float* Kr = Kg + (size_t)(jt * FBN + r) * 64;
        const float* Vr = Vg + (size_t)(jt * FBN + r) * 64;
#pragma unroll
        for (int i = 0; i < 4; i++) {
            int qq = qb + i;
            int ph = (qq & 8) | ((qq ^ (r & 7)) & 7);
            CP16(stK + r * 256 + ph * 16, Kr + qq * 4);
        }
#pragma unroll
        for (int i = 0; i < 4; i++) {
            int qq = qb + i;
            CP16(stV + r * 288 + qq * 16, Vr + qq * 4);
        }
    };
    load_kv(0); CP_COMMIT();
    load_kv(1); CP_COMMIT();
    CP_WAIT(1);
    __syncthreads();

    // ---- Q fragments (tf32, persistent) -----------------------------------
    const int rx   = lane & 7;
    const int aq   = (lane >> 4) & 1;
    const int arow = ((lane >> 3) & 1) * 8 + rx;
    uint32_t qf[8][4];
    {
        uint32_t base = S0 + QS_OFF + (w * 16 + arow) * 256;
#pragma unroll
        for (int ks = 0; ks < 8; ks++) {
            int qq = ks * 2 + aq;
            ldsm4(qf[ks], base + (((qq & 8) | ((qq ^ rx) & 7)) << 4));
#pragma unroll
            for (int i = 0; i < 4; i++) qf[ks][i] = f2tf(qf[ks][i]);
        }
    }

    const int g  = lane >> 2, t4 = lane & 3;
    const int bq   = (lane >> 3) & 1;
    const int brow = ((lane >> 4) & 1) * 8 + rx;
    const int row0 = q0 + w * 16 + g;       // this lane's rows: row0, row0+8

    float o[8][4];
#pragma unroll
    for (int nt = 0; nt < 8; nt++)
#pragma unroll
        for (int i = 0; i < 4; i++) o[nt][i] = 0.0f;
    float mrow[2] = { -1e30f, -1e30f };
    float lrow[2] = { 0.0f, 0.0f };

    const float sc = 0.125f;   // 1/sqrt(64)

    for (int jt = 0; jt < ntiles; jt++) {
        if (jt > 0) {
            CP_WAIT(0);
            __syncthreads();
            if (jt + 1 < ntiles) { load_kv(jt + 1); CP_COMMIT(); }
        }
        const int j0 = jt * FBN;
        // warp fully masked for this tile? (all cols > all rows)
        if (j0 > q0 + w * 16 + 15) continue;

        const uint32_t stK = S0 + KS_OFF + (jt & 1) * 16384;
        const float* Vsp = (const float*)(sm + VS_OFF + (jt & 1) * 18432);

        // ---- S = Q K^T ----------------------------------------------------
        float s[8][4];
#pragma unroll
        for (int nt = 0; nt < 8; nt++)
#pragma unroll
            for (int i = 0; i < 4; i++) s[nt][i] = 0.0f;

#pragma unroll
        for (int ks = 0; ks < 8; ks++) {
            uint32_t kf[4][4];
            const int qq = ks * 2 + bq;
            const uint32_t ph = ((qq & 8) | ((qq ^ rx) & 7)) << 4;
#pragma unroll
            for (int np = 0; np < 4; np++)
                ldsm4(kf[np], stK + (np * 16 + brow) * 256 + ph);
#pragma unroll
            for (int np = 0; np < 4; np++)
#pragma unroll
                for (int i = 0; i < 4; i++) kf[np][i] = f2tf(kf[np][i]);
#pragma unroll
            for (int nt = 0; nt < 8; nt++)
                mma_tf32(s[nt], qf[ks],
                         kf[nt >> 1][(nt & 1) * 2],
                         kf[nt >> 1][(nt & 1) * 2 + 1]);
        }

        // ---- scale + causal mask + online softmax -------------------------
        const bool full_ok = (j0 + FBN - 1 <= q0 + w * 16);
        float rmax0 = -1e30f, rmax1 = -1e30f;
#pragma unroll
        for (int nt = 0; nt < 8; nt++) {
            const int c0 = j0 + nt * 8 + 2 * t4;
            s[nt][0] *= sc; s[nt][1] *= sc; s[nt][2] *= sc; s[nt][3] *= sc;
            if (!full_ok) {
                if (c0     > row0)     s[nt][0] = -1e30f;
                if (c0 + 1 > row0)     s[nt][1] = -1e30f;
                if (c0     > row0 + 8) s[nt][2] = -1e30f;
                if (c0 + 1 > row0 + 8) s[nt][3] = -1e30f;
            }
            rmax0 = fmaxf(rmax0, fmaxf(s[nt][0], s[nt][1]));
            rmax1 = fmaxf(rmax1, fmaxf(s[nt][2], s[nt][3]));
        }
        rmax0 = fmaxf(rmax0, __shfl_xor_sync(0xffffffffu, rmax0, 1));
        rmax0 = fmaxf(rmax0, __shfl_xor_sync(0xffffffffu, rmax0, 2));
        rmax1 = fmaxf(rmax1, __shfl_xor_sync(0xffffffffu, rmax1, 1));
        rmax1 = fmaxf(rmax1, __shfl_xor_sync(0xffffffffu, rmax1, 2));

        const float mn0 = fmaxf(mrow[0], rmax0);
        const float mn1 = fmaxf(mrow[1], rmax1);
        const float al0 = __expf(mrow[0] - mn0);
        const float al1 = __expf(mrow[1] - mn1);
        float rs0 = 0.0f, rs1 = 0.0f;
#pragma unroll
        for (int nt = 0; nt < 8; nt++) {
            s[nt][0] = __expf(s[nt][0] - mn0);
            s[nt][1] = __expf(s[nt][1] - mn0);
            s[nt][2] = __expf(s[nt][2] - mn1);
            s[nt][3] = __expf(s[nt][3] - mn1);
            rs0 += s[nt][0] + s[nt][1];
            rs1 += s[nt][2] + s[nt][3];
        }
        rs0 += __shfl_xor_sync(0xffffffffu, rs0, 1);
        rs0 += __shfl_xor_sync(0xffffffffu, rs0, 2);
        rs1 += __shfl_xor_sync(0xffffffffu, rs1, 1);
        rs1 += __shfl_xor_sync(0xffffffffu, rs1, 2);
        lrow[0] = lrow[0] * al0 + rs0;  mrow[0] = mn0;
        lrow[1] = lrow[1] * al1 + rs1;  mrow[1] = mn1;
#pragma unroll
        for (int nt = 0; nt < 8; nt++) {
            o[nt][0] *= al0; o[nt][1] *= al0;
            o[nt][2] *= al1; o[nt][3] *= al1;
        }

        // ---- P -> smem (per-warp private rows), reload as a-frags ---------
        __syncwarp();
        {
            const int r0l = w * 16 + g;
#pragma unroll
            for (int nt = 0; nt < 8; nt++) {
                const int c  = nt * 8 + 2 * t4;
                const int qq = c >> 2;
                const int ph = (qq & 8) | ((qq ^ g) & 7);
                const uint32_t off = ph * 16 + (c & 3) * 4;
                float2 p0; p0.x = s[nt][0]; p0.y = s[nt][1];
                float2 p1; p1.x = s[nt][2]; p1.y = s[nt][3];
                *(float2*)(sm + QS_OFF + r0l * 256 + off)       = p0;
                *(float2*)(sm + QS_OFF + (r0l + 8) * 256 + off) = p1;
            }
        }
        __syncwarp();

        // ---- O += P V -----------------------------------------------------
        {
            const uint32_t pbase = S0 + QS_OFF + (w * 16 + arow) * 256;
#pragma unroll
            for (int ks = 0; ks < 8; ks++) {
                uint32_t pf[4];
                const int qq = ks * 2 + aq;
                ldsm4(pf, pbase + (((qq & 8) | ((qq ^ rx) & 7)) << 4));
#pragma unroll
                for (int i = 0; i < 4; i++) pf[i] = f2tf(pf[i]);
#pragma unroll
                for (int nt = 0; nt < 8; nt++) {
                    const float bv0 = Vsp[(ks * 8 + t4) * 72 + nt * 8 + g];
                    const float bv1 = Vsp[(ks * 8 + t4 + 4) * 72 + nt * 8 + g];
                    mma_tf32(o[nt], pf, f2tf_f(bv0), f2tf_f(bv1));
                }
            }
        }
        __syncwarp();
    }

    // ---- normalize + write g_o[token][h*64 + dk] --------------------------
    const int b = bh >> 4, h = bh & 15;
    const float inv0 = 1.0f / lrow[0];
    const float inv1 = 1.0f / lrow[1];
#pragma unroll
    for (int nt = 0; nt < 8; nt++) {
        const int col = h * 64 + nt * 8 + 2 * t4;
        float2 v0; v0.x = o[nt][0] * inv0; v0.y = o[nt][1] * inv0;
        float2 v1; v1.x = o[nt][2] * inv1; v1.y = o[nt][3] * inv1;
        *(float2*)&g_o[(size_t)(b * SS + row0) * DD + col]     = v0;
        *(float2*)&g_o[(size_t)(b * SS + row0 + 8) * DD + col] = v1;
    }
}

// ---------------------------------------------------------------------------
extern "C" void kernel_launch(void* const* d_in, const int* in_sizes, int n_in,
                              void* d_out, int out_size)
{
    const float* x      = (const float*)d_in[0];
    // d_in[1] = mask (causal tril; structure exploited directly)
    const float* w_qkv  = (const float*)d_in[2];
    const float* b_qkv  = (const float*)d_in[3];
    const float* w_o    = (const float*)d_in[4];
    const float* b_o    = (const float*)d_in[5];
    float* out          = (float*)d_out;

    (void)in_sizes; (void)n_in; (void)out_size;

    cudaFuncSetAttribute(gemm_mma<0>, cudaFuncAttributeMaxDynamicSharedMemorySize, GEMM_SMEM);
    cudaFuncSetAttribute(gemm_mma<1>, cudaFuncAttributeMaxDynamicSharedMemorySize, GEMM_SMEM);
    cudaFuncSetAttribute(flash_mma_kernel, cudaFuncAttributeMaxDynamicSharedMemorySize, FLASH_SMEM);

    dim3 g1(N3 / 128, NTOK / 128);       // 24 x 32
    gemm_mma<0><<<g1, 256, GEMM_SMEM>>>(x, w_qkv, b_qkv, nullptr);

    dim3 g2(SS / FBM, BB * HH);          // 16 x 32
    flash_mma_kernel<<<g2, 256, FLASH_SMEM>>>();

    dim3 g3(DD / 128, NTOK / 128);       // 8 x 32
    gemm_mma<1><<<g3, 256, GEMM_SMEM>>>(nullptr, w_o, b_o, out);
}

// round 7
// speedup vs baseline: 4.1958x; 1.1931x over previous
#include <cuda_runtime.h>
#include <cuda_bf16.h>
#include <cstdint>

// Problem constants
#define BB   2
#define SS   2048
#define DD   1024
#define HH   16
#define DK   64
#define N3   3072   // 3*D
#define NTOK 4096   // B*S

// Scratch (allocation-free rule: __device__ globals)
__device__ float g_q[BB * HH * SS * DK];   // [bh, s, dk]   tf32-rounded
__device__ float g_k[BB * HH * SS * DK];   // tf32-rounded
__device__ float g_v[BB * HH * SS * DK];   // tf32-rounded
__device__ float g_o[NTOK * DD];           // [token, h*64+d] tf32-rounded
__device__ float g_xr[NTOK * DD];          // x, tf32-rounded
__device__ float g_wqkvr[N3 * DD];         // w_qkv, tf32-rounded
__device__ float g_wor[DD * DD];           // w_o, tf32-rounded

// ---------------------------------------------------------------------------
// PTX helpers — base sm_80+ ISA only (harness targets plain sm_103: NO tcgen05)
// ---------------------------------------------------------------------------
__device__ __forceinline__ uint32_t smem_u32(const void* p) {
    uint32_t a;
    asm("{ .reg .u64 t; cvta.to.shared.u64 t, %1; cvt.u32.u64 %0, t; }"
        : "=r"(a) : "l"(p));
    return a;
}

#define CP16(dst, src) \
    asm volatile("cp.async.cg.shared.global [%0], [%1], 16;" :: "r"(dst), "l"(src))
#define CP_COMMIT() asm volatile("cp.async.commit_group;" ::: "memory")
#define CP_WAIT(n)  asm volatile("cp.async.wait_group %0;" :: "n"(n) : "memory")

__device__ __forceinline__ void ldsm4(uint32_t* r, uint32_t addr) {
    asm volatile("ldmatrix.sync.aligned.m8n8.x4.shared.b16 {%0,%1,%2,%3}, [%4];"
        : "=r"(r[0]), "=r"(r[1]), "=r"(r[2]), "=r"(r[3]) : "r"(addr));
}

// f32 -> tf32 round-to-nearest (value-idempotent: producer-side rounding is
// bit-identical to consumer-side rounding, so hot loops can skip it)
__device__ __forceinline__ uint32_t f2tf(uint32_t x) {
    uint32_t r;
    asm("cvt.rna.tf32.f32 %0, %1;" : "=r"(r) : "f"(__uint_as_float(x)));
    return r;
}
__device__ __forceinline__ float f2tf_val(float x) {
    uint32_t r;
    asm("cvt.rna.tf32.f32 %0, %1;" : "=r"(r) : "f"(x));
    return __uint_as_float(r);
}

__device__ __forceinline__ void mma_tf32(float* c, const uint32_t* a,
                                         uint32_t b0, uint32_t b1) {
    asm volatile(
        "mma.sync.aligned.m16n8k8.row.col.f32.tf32.tf32.f32 "
        "{%0,%1,%2,%3}, {%4,%5,%6,%7}, {%8,%9}, {%0,%1,%2,%3};"
        : "+f"(c[0]), "+f"(c[1]), "+f"(c[2]), "+f"(c[3])
        : "r"(a[0]), "r"(a[1]), "r"(a[2]), "r"(a[3]), "r"(b0), "r"(b1));
}

// ---------------------------------------------------------------------------
// Kernel 0: elementwise tf32 pre-round (src -> dst), n % 1024 == 0
// ---------------------------------------------------------------------------
__global__ __launch_bounds__(256) void round_tf32_kernel(
    const float* __restrict__ src, float* __restrict__ dst)
{
    const int i = (blockIdx.x * 256 + threadIdx.x) * 4;
    float4 v = *(const float4*)(src + i);
    v.x = f2tf_val(v.x); v.y = f2tf_val(v.y);
    v.z = f2tf_val(v.z); v.w = f2tf_val(v.w);
    *(float4*)(dst + i) = v;
}

// ---------------------------------------------------------------------------
// tf32 mma.sync GEMM — inputs pre-rounded, NO in-loop cvt.
// MODE 0: A = g_xr, B = g_wqkvr; epilogue scatters tf32-rounded Q/K/V.
// MODE 1: A = g_o,  B = g_wor;   epilogue writes final Out (fp32 + bias).
// ---------------------------------------------------------------------------
#define STAGES      3
#define STAGE_BYTES 32768           // A tile 16KB + B tile 16KB
#define NCHUNK      32              // K=1024 / 32
#define GEMM_SMEM   (1024 + STAGES * STAGE_BYTES)

template<int MODE>
__global__ __launch_bounds__(256, 2) void gemm_mma(
    const float* __restrict__ bias, float* __restrict__ Out)
{
    extern __shared__ __align__(16) char smem_raw[];
    const uint32_t sb  = smem_u32(smem_raw);
    const uint32_t st0 = (sb + 1023u) & ~1023u;

    const int t    = threadIdx.x;
    const int lane = t & 31;
    const int wid  = t >> 5;
    const int wm   = wid & 1;
    const int wn   = wid >> 1;
    const int m0   = blockIdx.y * 128;
    const int n0   = blockIdx.x * 128;

    const float* A  = (MODE == 1) ? g_o : g_xr;
    const float* Bw = (MODE == 1) ? g_wor : g_wqkvr;

    const int rb = t >> 3;
    const int q  = t & 7;
    const float* Abase = A  + (size_t)m0 * DD + q * 4;
    const float* Bbase = Bw + (size_t)n0 * DD + q * 4;

    auto load_chunk = [&](int c) {
        const uint32_t st = st0 + (c % STAGES) * STAGE_BYTES;
        const float* Ac = Abase + c * 32;
        const float* Bc = Bbase + c * 32;
#pragma unroll
        for (int it = 0; it < 4; it++) {
            int r = rb + it * 32;
            CP16(st + r * 128 + ((q ^ (r & 7)) << 4), Ac + (size_t)r * DD);
        }
#pragma unroll
        for (int it = 0; it < 4; it++) {
            int r = rb + it * 32;
            CP16(st + 16384 + r * 128 + ((q ^ (r & 7)) << 4), Bc + (size_t)r * DD);
        }
    };

    const int rx   = lane & 7;
    const int aq   = (lane >> 4) & 1;
    const int arow = ((lane >> 3) & 1) * 8 + rx;
    uint32_t arow_off[4];
#pragma unroll
    for (int mt = 0; mt < 4; mt++)
        arow_off[mt] = (wm * 64 + mt * 16 + arow) * 128;
    const int bq   = (lane >> 3) & 1;
    const int brow = ((lane >> 4) & 1) * 8 + rx;
    uint32_t brow_off[2];
#pragma unroll
    for (int np = 0; np < 2; np++)
        brow_off[np] = (wn * 32 + np * 16 + brow) * 128;

    float acc[4][4][4];
#pragma unroll
    for (int mt = 0; mt < 4; mt++)
#pragma unroll
        for (int nt = 0; nt < 4; nt++)
#pragma unroll
            for (int i = 0; i < 4; i++) acc[mt][nt][i] = 0.0f;

    load_chunk(0); CP_COMMIT();
    load_chunk(1); CP_COMMIT();

    for (int c = 0; c < NCHUNK; c++) {
        CP_WAIT(1);
        __syncthreads();

        if (c + 2 < NCHUNK) load_chunk(c + 2);
        CP_COMMIT();

        const uint32_t stA = st0 + (c % STAGES) * STAGE_BYTES;
        const uint32_t stB = stA + 16384;
#pragma unroll
        for (int ks = 0; ks < 4; ks++) {
            uint32_t a[4][4], b[2][4];
#pragma unroll
            for (int mt = 0; mt < 4; mt++)
                ldsm4(a[mt], stA + arow_off[mt] + (((ks * 2 + aq) ^ rx) << 4));
#pragma unroll
            for (int np = 0; np < 2; np++)
                ldsm4(b[np], stB + brow_off[np] + (((ks * 2 + bq) ^ rx) << 4));
#pragma unroll
            for (int mt = 0; mt < 4; mt++)
#pragma unroll
                for (int nt = 0; nt < 4; nt++)
                    mma_tf32(acc[mt][nt],
                             a[mt],
                             b[nt >> 1][(nt & 1) * 2],
                             b[nt >> 1][(nt & 1) * 2 + 1]);
        }
    }

    const int g  = lane >> 2;
    const int t4 = lane & 3;
#pragma unroll
    for (int mt = 0; mt < 4; mt++) {
        const int m = m0 + wm * 64 + mt * 16 + g;
#pragma unroll
        for (int nt = 0; nt < 4; nt++) {
            const int n = n0 + wn * 32 + nt * 8 + 2 * t4;
            const float2 b2 = *(const float2*)&bias[n];
            float2 v0, v1;
            v0.x = acc[mt][nt][0] + b2.x; v0.y = acc[mt][nt][1] + b2.y;
            v1.x = acc[mt][nt][2] + b2.x; v1.y = acc[mt][nt][3] + b2.y;
            if (MODE == 1) {
                *(float2*)&Out[(size_t)m * DD + n]       = v0;
                *(float2*)&Out[(size_t)(m + 8) * DD + n] = v1;
            } else {
                // producer-side tf32 rounding: flash consumes Q/K/V as MMA
                // operands only, so this is bit-identical to rounding there
                v0.x = f2tf_val(v0.x); v0.y = f2tf_val(v0.y);
                v1.x = f2tf_val(v1.x); v1.y = f2tf_val(v1.y);
                const int sel = n >> 10;
                const int h   = (n & 1023) >> 6;
                const int dk  = n & 63;
                float* dst = (sel == 0) ? g_q : ((sel == 1) ? g_k : g_v);
                const int b0i = m >> 11, s0 = m & 2047;
                *(float2*)&dst[((size_t)(b0i * HH + h) * SS + s0) * DK + dk] = v0;
                const int b1i = (m + 8) >> 11, s1 = (m + 8) & 2047;
                *(float2*)&dst[((size_t)(b1i * HH + h) * SS + s1) * DK + dk] = v1;
            }
        }
    }
}

// ---------------------------------------------------------------------------
// Kernel 2: flash attention on tf32 mma.sync.
// Q/K/V arrive pre-rounded -> NO cvt in the hot loop (only P fragments).
// ---------------------------------------------------------------------------
#define FBM 128
#define FBN 64
#define QS_OFF  0                       // 128 rows x 256B (Q, then P)
#define KS_OFF  32768                   // 2 stages x 64 x 256B
#define VS_OFF  (32768 + 32768)         // 2 stages x 64 x 288B
#define FLASH_SMEM (VS_OFF + 2 * 18432) // 102400

__global__ __launch_bounds__(256) void flash_mma_kernel()
{
    extern __shared__ __align__(16) char sm[];
    const uint32_t S0 = smem_u32(sm);

    const int t    = threadIdx.x;
    const int lane = t & 31;
    const int w    = t >> 5;
    const int bh   = blockIdx.y;
    const int qt   = (int)gridDim.x - 1 - (int)blockIdx.x;   // heavy first
    const int q0   = qt * FBM;

    const float* Qg = g_q + (size_t)(bh * SS + q0) * DK;
    const float* Kg = g_k + (size_t)bh * SS * DK;
    const float* Vg = g_v + (size_t)bh * SS * DK;

    const int ntiles = q0 / FBN + 2;

    // ---- Q tile -> smem (swizzled 256B rows) ------------------------------
    {
        int r = t >> 1, h8 = (t & 1) * 8;
#pragma unroll
        for (int i = 0; i < 8; i++) {
            int qq = h8 + i;
            int ph = (qq & 8) | ((qq ^ (r & 7)) & 7);
            CP16(S0 + QS_OFF + r * 256 + ph * 16, Qg + r * 64 + qq * 4);
        }
    }
    auto load_kv = [&](int jt) {
        uint32_t stK = S0 + KS_OFF + (jt & 1) * 16384;
        uint32_t stV = S0 + VS_OFF + (jt & 1) * 18432;
        int r = t >> 2, qb = (t & 3) * 4;
        const float* Kr = Kg + (size_t)(jt * FBN + r) * 64;
        const float* Vr = Vg + (size_t)(jt * FBN + r) * 64;
#pragma unroll
        for (int i = 0; i < 4; i++) {
            int qq = qb + i;
            int ph = (qq & 8) | ((qq ^ (r & 7)) & 7);
            CP16(stK + r * 256 + ph * 16, Kr + qq * 4);
        }
#pragma unroll
        for (int i = 0; i < 4; i++) {
            int qq = qb + i;
            CP16(stV + r * 288 + qq * 16, Vr + qq * 4);
        }
    };
    load_kv(0); CP_COMMIT();
    load_kv(1); CP_COMMIT();
    CP_WAIT(1);
    __syncthreads();

    // ---- Q fragments (pre-rounded tf32, persistent) -----------------------
    const int rx   = lane & 7;
    const int aq   = (lane >> 4) & 1;
    const int arow = ((lane >> 3) & 1) * 8 + rx;
    uint32_t qf[8][4];
    {
        uint32_t base = S0 + QS_OFF + (w * 16 + arow) * 256;
#pragma unroll
        for (int ks = 0; ks < 8; ks++) {
            int qq = ks * 2 + aq;
            ldsm4(qf[ks], base + (((qq & 8) | ((qq ^ rx) & 7)) << 4));
        }
    }

    const int g  = lane >> 2, t4 = lane & 3;
    const int bq   = (lane >> 3) & 1;
    const int brow = ((lane >> 4) & 1) * 8 + rx;
    const int row0 = q0 + w * 16 + g;       // this lane's rows: row0, row0+8

    float o[8][4];
#pragma unroll
    for (int nt = 0; nt < 8; nt++)
#pragma unroll
        for (int i = 0; i < 4; i++) o[nt][i] = 0.0f;
    float mrow[2] = { -1e30f, -1e30f };
    float lrow[2] = { 0.0f, 0.0f };

    const float sc = 0.125f;   // 1/sqrt(64)

    for (int jt = 0; jt < ntiles; jt++) {
        if (jt > 0) {
            CP_WAIT(0);
            __syncthreads();
            if (jt + 1 < ntiles) { load_kv(jt + 1); CP_COMMIT(); }
        }
        const int j0 = jt * FBN;
        // warp fully masked for this tile? (all cols > all rows)
        if (j0 > q0 + w * 16 + 15) continue;

        const uint32_t stK = S0 + KS_OFF + (jt & 1) * 16384;
        const float* Vsp = (const float*)(sm + VS_OFF + (jt & 1) * 18432);

        // ---- S = Q K^T ----------------------------------------------------
        float s[8][4];
#pragma unroll
        for (int nt = 0; nt < 8; nt++)
#pragma unroll
            for (int i = 0; i < 4; i++) s[nt][i] = 0.0f;

#pragma unroll
        for (int ks = 0; ks < 8; ks++) {
            uint32_t kf[4][4];
            const int qq = ks * 2 + bq;
            const uint32_t ph = ((qq & 8) | ((qq ^ rx) & 7)) << 4;
#pragma unroll
            for (int np = 0; np < 4; np++)
                ldsm4(kf[np], stK + (np * 16 + brow) * 256 + ph);
#pragma unroll
            for (int nt = 0; nt < 8; nt++)
                mma_tf32(s[nt], qf[ks],
                         kf[nt >> 1][(nt & 1) * 2],
                         kf[nt >> 1][(nt & 1) * 2 + 1]);
        }

        // ---- scale + causal mask + online softmax -------------------------
        const bool full_ok = (j0 + FBN - 1 <= q0 + w * 16);
        float rmax0 = -1e30f, rmax1 = -1e30f;
#pragma unroll
        for (int nt = 0; nt < 8; nt++) {
            const int c0 = j0 + nt * 8 + 2 * t4;
            s[nt][0] *= sc; s[nt][1] *= sc; s[nt][2] *= sc; s[nt][3] *= sc;
            if (!full_ok) {
                if (c0     > row0)     s[nt][0] = -1e30f;
                if (c0 + 1 > row0)     s[nt][1] = -1e30f;
                if (c0     > row0 + 8) s[nt][2] = -1e30f;
                if (c0 + 1 > row0 + 8) s[nt][3] = -1e30f;
            }
            rmax0 = fmaxf(rmax0, fmaxf(s[nt][0], s[nt][1]));
            rmax1 = fmaxf(rmax1, fmaxf(s[nt][2], s[nt][3]));
        }
        rmax0 = fmaxf(rmax0, __shfl_xor_sync(0xffffffffu, rmax0, 1));
        rmax0 = fmaxf(rmax0, __shfl_xor_sync(0xffffffffu, rmax0, 2));
        rmax1 = fmaxf(rmax1, __shfl_xor_sync(0xffffffffu, rmax1, 1));
        rmax1 = fmaxf(rmax1, __shfl_xor_sync(0xffffffffu, rmax1, 2));

        const float mn0 = fmaxf(mrow[0], rmax0);
        const float mn1 = fmaxf(mrow[1], rmax1);
        const float al0 = __expf(mrow[0] - mn0);
        const float al1 = __expf(mrow[1] - mn1);
        float rs0 = 0.0f, rs1 = 0.0f;
#pragma unroll
        for (int nt = 0; nt < 8; nt++) {
            s[nt][0] = __expf(s[nt][0] - mn0);
            s[nt][1] = __expf(s[nt][1] - mn0);
            s[nt][2] = __expf(s[nt][2] - mn1);
            s[nt][3] = __expf(s[nt][3] - mn1);
            rs0 += s[nt][0] + s[nt][1];
            rs1 += s[nt][2] + s[nt][3];
        }
        rs0 += __shfl_xor_sync(0xffffffffu, rs0, 1);
        rs0 += __shfl_xor_sync(0xffffffffu, rs0, 2);
        rs1 += __shfl_xor_sync(0xffffffffu, rs1, 1);
        rs1 += __shfl_xor_sync(0xffffffffu, rs1, 2);
        lrow[0] = lrow[0] * al0 + rs0;  mrow[0] = mn0;
        lrow[1] = lrow[1] * al1 + rs1;  mrow[1] = mn1;
#pragma unroll
        for (int nt = 0; nt < 8; nt++) {
            o[nt][0] *= al0; o[nt][1] *= al0;
            o[nt][2] *= al1; o[nt][3] *= al1;
        }

        // ---- P -> smem (per-warp private rows), reload as a-frags ---------
        __syncwarp();
        {
            const int r0l = w * 16 + g;
#pragma unroll
            for (int nt = 0; nt < 8; nt++) {
                const int c  = nt * 8 + 2 * t4;
                const int qq = c >> 2;
                const int ph = (qq & 8) | ((qq ^ g) & 7);
                const uint32_t off = ph * 16 + (c & 3) * 4;
                float2 p0; p0.x = s[nt][0]; p0.y = s[nt][1];
                float2 p1; p1.x = s[nt][2]; p1.y = s[nt][3];
                *(float2*)(sm + QS_OFF + r0l * 256 + off)       = p0;
                *(float2*)(sm + QS_OFF + (r0l + 8) * 256 + off) = p1;
            }
        }
        __syncwarp();

        // ---- O += P V  (V pre-rounded; only P needs cvt) ------------------
        {
            const uint32_t pbase = S0 + QS_OFF + (w * 16 + arow) * 256;
#pragma unroll
            for (int ks = 0; ks < 8; ks++) {
                uint32_t pf[4];
                const int qq = ks * 2 + aq;
                ldsm4(pf, pbase + (((qq & 8) | ((qq ^ rx) & 7)) << 4));
#pragma unroll
                for (int i = 0; i < 4; i++) pf[i] = f2tf(pf[i]);
#pragma unroll
                for (int nt = 0; nt < 8; nt++) {
                    const uint32_t bv0 =
                        __float_as_uint(Vsp[(ks * 8 + t4) * 72 + nt * 8 + g]);
                    const uint32_t bv1 =
                        __float_as_uint(Vsp[(ks * 8 + t4 + 4) * 72 + nt * 8 + g]);
                    mma_tf32(o[nt], pf, bv0, bv1);
                }
            }
        }
        __syncwarp();
    }

    // ---- normalize + write g_o (tf32-rounded: oproj consumes via MMA) -----
    const int b = bh >> 4, h = bh & 15;
    const float inv0 = 1.0f / lrow[0];
    const float inv1 = 1.0f / lrow[1];
#pragma unroll
    for (int nt = 0; nt < 8; nt++) {
        const int col = h * 64 + nt * 8 + 2 * t4;
        float2 v0, v1;
        v0.x = f2tf_val(o[nt][0] * inv0); v0.y = f2tf_val(o[nt][1] * inv0);
        v1.x = f2tf_val(o[nt][2] * inv1); v1.y = f2tf_val(o[nt][3] * inv1);
        *(float2*)&g_o[(size_t)(b * SS + row0) * DD + col]     = v0;
        *(float2*)&g_o[(size_t)(b * SS + row0 + 8) * DD + col] = v1;
    }
}

// ---------------------------------------------------------------------------
extern "C" void kernel_launch(void* const* d_in, const int* in_sizes, int n_in,
                              void* d_out, int out_size)
{
    const float* x      = (const float*)d_in[0];
    // d_in[1] = mask (causal tril; structure exploited directly)
    const float* w_qkv  = (const float*)d_in[2];
    const float* b_qkv  = (const float*)d_in[3];
    const float* w_o    = (const float*)d_in[4];
    const float* b_o    = (const float*)d_in[5];
    float* out          = (float*)d_out;

    (void)in_sizes; (void)n_in; (void)out_size;

    cudaFuncSetAttribute(gemm_mma<0>, cudaFuncAttributeMaxDynamicSharedMemorySize, GEMM_SMEM);
    cudaFuncSetAttribute(gemm_mma<1>, cudaFuncAttributeMaxDynamicSharedMemorySize, GEMM_SMEM);
    cudaFuncSetAttribute(flash_mma_kernel, cudaFuncAttributeMaxDynamicSharedMemorySize, FLASH_SMEM);

    float* d_xr, *d_wqkvr, *d_wor;
    cudaGetSymbolAddress((void**)&d_xr,    g_xr);
    cudaGetSymbolAddress((void**)&d_wqkvr, g_wqkvr);
    cudaGetSymbolAddress((void**)&d_wor,   g_wor);

    // pre-round all MMA inputs to tf32 (producer-side rounding)
    round_tf32_kernel<<<NTOK * DD / 1024, 256>>>(x,      d_xr);
    round_tf32_kernel<<<N3 * DD   / 1024, 256>>>(w_qkv,  d_wqkvr);
    round_tf32_kernel<<<DD * DD   / 1024, 256>>>(w_o,    d_wor);

    dim3 g1(N3 / 128, NTOK / 128);       // 24 x 32
    gemm_mma<0><<<g1, 256, GEMM_SMEM>>>(b_qkv, nullptr);

    dim3 g2(SS / FBM, BB * HH);          // 16 x 32
    flash_mma_kernel<<<g2, 256, FLASH_SMEM>>>();

    dim3 g3(DD / 128, NTOK / 128);       // 8 x 32
    gemm_mma<1><<<g3, 256, GEMM_SMEM>>>(b_o, out);
}

// round 9
// speedup vs baseline: 7.6374x; 1.8203x over previous
#include <cuda_runtime.h>
#include <cuda_fp16.h>
#include <cstdint>

// Problem constants
#define BB   2
#define SS   2048
#define DD   1024
#define HH   16
#define DK   64
#define N3   3072   // 3*D
#define NTOK 4096   // B*S

// Scratch (allocation-free rule: __device__ globals) — all fp16 MMA operands
__device__ __half g_qh[BB * HH * SS * DK];   // [bh, s, dk]
__device__ __half g_kh[BB * HH * SS * DK];
__device__ __half g_vh[BB * HH * SS * DK];
__device__ __half g_oh[NTOK * DD];           // [token, h*64+d]
__device__ __half g_xh[NTOK * DD];           // x -> fp16
__device__ __half g_wqkvh[N3 * DD];          // w_qkv -> fp16
__device__ __half g_woh[DD * DD];            // w_o -> fp16

// ---------------------------------------------------------------------------
// PTX helpers — base sm_80+ ISA only (harness targets plain sm_103: NO tcgen05)
// ---------------------------------------------------------------------------
__device__ __forceinline__ uint32_t smem_u32(const void* p) {
    uint32_t a;
    asm("{ .reg .u64 t; cvta.to.shared.u64 t, %1; cvt.u32.u64 %0, t; }"
        : "=r"(a) : "l"(p));
    return a;
}

#define CP16(dst, src) \
    asm volatile("cp.async.cg.shared.global [%0], [%1], 16;" :: "r"(dst), "l"(src))
#define CP_COMMIT() asm volatile("cp.async.commit_group;" ::: "memory")
#define CP_WAIT(n)  asm volatile("cp.async.wait_group %0;" :: "n"(n) : "memory")

__device__ __forceinline__ void ldsm4(uint32_t* r, uint32_t addr) {
    asm volatile("ldmatrix.sync.aligned.m8n8.x4.shared.b16 {%0,%1,%2,%3}, [%4];"
        : "=r"(r[0]), "=r"(r[1]), "=r"(r[2]), "=r"(r[3]) : "r"(addr));
}
__device__ __forceinline__ void ldsm4t(uint32_t* r, uint32_t addr) {
    asm volatile("ldmatrix.sync.aligned.m8n8.x4.trans.shared.b16 {%0,%1,%2,%3}, [%4];"
        : "=r"(r[0]), "=r"(r[1]), "=r"(r[2]), "=r"(r[3]) : "r"(addr));
}

__device__ __forceinline__ void mma_f16(float* c, const uint32_t* a,
                                        uint32_t b0, uint32_t b1) {
    asm volatile(
        "mma.sync.aligned.m16n8k16.row.col.f32.f16.f16.f32 "
        "{%0,%1,%2,%3}, {%4,%5,%6,%7}, {%8,%9}, {%0,%1,%2,%3};"
        : "+f"(c[0]), "+f"(c[1]), "+f"(c[2]), "+f"(c[3])
        : "r"(a[0]), "r"(a[1]), "r"(a[2]), "r"(a[3]), "r"(b0), "r"(b1));
}

// ---------------------------------------------------------------------------
// Kernel 0: fp32 -> fp16 convert (producer-side rounding), n % 1024 == 0
// ---------------------------------------------------------------------------
__global__ __launch_bounds__(256) void to_half_kernel(
    const float* __restrict__ src, __half2* __restrict__ dst)
{
    const int i = blockIdx.x * 256 + threadIdx.x;     // half2-pair index
    float4 v = *(const float4*)(src + i * 4);
    __half2 h0 = __floats2half2_rn(v.x, v.y);
    __half2 h1 = __floats2half2_rn(v.z, v.w);
    dst[i * 2]     = h0;
    dst[i * 2 + 1] = h1;
}

// ---------------------------------------------------------------------------
// fp16 mma.sync GEMM: C[m,n] = sum_k A[m,k]*W[n,k] + bias[n]
// MODE 0: A = g_xh, B = g_wqkvh; epilogue scatters fp16 Q/K/V.
// MODE 1: A = g_oh, B = g_woh;   epilogue writes final fp32 Out + bias.
// Block tile 128x128, 8 warps (warp tile 64x32), K-chunks of 64 halves
// (128B rows, XOR-16B swizzle), 3-stage cp.async pipeline.
// ---------------------------------------------------------------------------
#define STAGES      3
#define STAGE_BYTES 32768           // A tile 16KB + B tile 16KB (fp16)
#define NCHUNK      16              // K=1024 / 64
#define GEMM_SMEM   (1024 + STAGES * STAGE_BYTES)

template<int MODE>
__global__ __launch_bounds__(256, 2) void gemm_mma(
    const float* __restrict__ bias, float* __restrict__ Out)
{
    extern __shared__ __align__(16) char smem_raw[];
    const uint32_t sb  = smem_u32(smem_raw);
    const uint32_t st0 = (sb + 1023u) & ~1023u;

    const int t    = threadIdx.x;
    const int lane = t & 31;
    const int wid  = t >> 5;
    const int wm   = wid & 1;
    const int wn   = wid >> 1;
    const int m0   = blockIdx.y * 128;
    const int n0   = blockIdx.x * 128;

    const __half* A  = (MODE == 1) ? g_oh : g_xh;
    const __half* Bw = (MODE == 1) ? g_woh : g_wqkvh;

    // ---- cp.async: 8 x 16B per thread per chunk ---------------------------
    const int rb = t >> 3;            // base row 0..31
    const int q  = t & 7;             // quad (8 halves) within 128B row
    const __half* Abase = A  + (size_t)m0 * DD + q * 8;
    const __half* Bbase = Bw + (size_t)n0 * DD + q * 8;

    auto load_chunk = [&](int c) {
        const uint32_t st = st0 + (c % STAGES) * STAGE_BYTES;
        const __half* Ac = Abase + c * 64;
        const __half* Bc = Bbase + c * 64;
#pragma unroll
        for (int it = 0; it < 4; it++) {
            int r = rb + it * 32;
            CP16(st + r * 128 + ((q ^ (r & 7)) << 4), Ac + (size_t)r * DD);
        }
#pragma unroll
        for (int it = 0; it < 4; it++) {
            int r = rb + it * 32;
            CP16(st + 16384 + r * 128 + ((q ^ (r & 7)) << 4), Bc + (size_t)r * DD);
        }
    };

    // ---- ldmatrix geometry (m16n8k16) -------------------------------------
    const int rx = lane & 7;
    const int r8 = ((lane >> 3) & 1) * 8;   // A: +8 rows for frag tiles 1,3
    const int qh = (lane >> 4) & 1;         // A: +1 quad for frag tiles 2,3
    const int rB8 = ((lane >> 4) & 1) * 8;  // B: +8 n-rows for tiles 2,3
    const int qB  = (lane >> 3) & 1;        // B: +1 quad for tiles 1,3

    float acc[4][4][4];
#pragma unroll
    for (int mt = 0; mt < 4; mt++)
#pragma unroll
        for (int nt = 0; nt < 4; nt++)
#pragma unroll
            for (int i = 0; i < 4; i++) acc[mt][nt][i] = 0.0f;

    load_chunk(0); CP_COMMIT();
    load_chunk(1); CP_COMMIT();

    for (int c = 0; c < NCHUNK; c++) {
        CP_WAIT(1);
        __syncthreads();

        if (c + 2 < NCHUNK) load_chunk(c + 2);
        CP_COMMIT();

        const uint32_t stA = st0 + (c % STAGES) * STAGE_BYTES;
        const uint32_t stB = stA + 16384;
#pragma unroll
        for (int ks = 0; ks < 4; ks++) {      // k16 steps within 64-half chunk
            uint32_t a[4][4], b[2][4];
            const uint32_t aph = ((2 * ks + qh) ^ rx) << 4;
            const uint32_t bph = ((2 * ks + qB) ^ rx) << 4;
#pragma unroll
            for (int mt = 0; mt < 4; mt++)
                ldsm4(a[mt], stA + (wm * 64 + mt * 16 + r8 + rx) * 128 + aph);
#pragma unroll
            for (int p = 0; p < 2; p++)
                ldsm4(b[p], stB + (wn * 32 + p * 16 + rB8 + rx) * 128 + bph);
#pragma unroll
            for (int mt = 0; mt < 4; mt++)
#pragma unroll
                for (int nt = 0; nt < 4; nt++)
                    mma_f16(acc[mt][nt], a[mt],
                            b[nt >> 1][(nt & 1) * 2],
                            b[nt >> 1][(nt & 1) * 2 + 1]);
        }
    }

    // ---- epilogue ---------------------------------------------------------
    const int g  = lane >> 2;
    const int t4 = lane & 3;
#pragma unroll
    for (int mt = 0; mt < 4; mt++) {
        const int m = m0 + wm * 64 + mt * 16 + g;
#pragma unroll
        for (int nt = 0; nt < 4; nt++) {
            const int n = n0 + wn * 32 + nt * 8 + 2 * t4;
            const float2 b2 = *(const float2*)&bias[n];
            float2 v0, v1;
            v0.x = acc[mt][nt][0] + b2.x; v0.y = acc[mt][nt][1] + b2.y;
            v1.x = acc[mt][nt][2] + b2.x; v1.y = acc[mt][nt][3] + b2.y;
            if (MODE == 1) {
                *(float2*)&Out[(size_t)m * DD + n]       = v0;
                *(float2*)&Out[(size_t)(m + 8) * DD + n] = v1;
            } else {
                // producer-side fp16 rounding: flash uses Q/K/V only as MMA ops
                const __half2 h0 = __floats2half2_rn(v0.x, v0.y);
                const __half2 h1 = __floats2half2_rn(v1.x, v1.y);
                const int sel = n >> 10;
                const int h   = (n & 1023) >> 6;
                const int dk  = n & 63;
                __half* dst = (sel == 0) ? g_qh : ((sel == 1) ? g_kh : g_vh);
                const int b0i = m >> 11, s0 = m & 2047;
                *(__half2*)&dst[((size_t)(b0i * HH + h) * SS + s0) * DK + dk] = h0;
                const int b1i = (m + 8) >> 11, s1 = (m + 8) & 2047;
                *(__half2*)&dst[((size_t)(b1i * HH + h) * SS + s1) * DK + dk] = h1;
            }
        }
    }
}

// ---------------------------------------------------------------------------
// Kernel 2: flash attention on fp16 mma.sync (m16n8k16).
// BLOCK_M=128, BLOCK_N=64, 8 warps (16 q-rows each), d=64.
// Q held as fp16 a-frags in regs; K double-buffered (ldmatrix b-frags);
// V row-major, b-frags via ldmatrix.trans; P round-trips through Q smem.
// smem: Q/P 16KB + K 2x8KB + V 2x8KB = 48KB.
// ---------------------------------------------------------------------------
#define FBM 128
#define FBN 64
#define QS_OFF  0
#define KS_OFF  16384
#define VS_OFF  32768
#define FLASH_SMEM 49152

__global__ __launch_bounds__(256) void flash_mma_kernel()
{
    extern __shared__ __align__(16) char sm[];
    const uint32_t S0 = smem_u32(sm);

    const int t    = threadIdx.x;
    const int lane = t & 31;
    const int w    = t >> 5;
    const int bh   = blockIdx.y;
    const int qt   = (int)gridDim.x - 1 - (int)blockIdx.x;   // heavy first
    const int q0   = qt * FBM;

    const __half* Qg = g_qh + (size_t)(bh * SS + q0) * DK;
    const __half* Kg = g_kh + (size_t)bh * SS * DK;
    const __half* Vg = g_vh + (size_t)bh * SS * DK;

    const int ntiles = q0 / FBN + 2;

    // ---- Q tile -> smem (128 rows x 128B, swizzled) -----------------------
    {
        int r = t >> 1, q4 = (t & 1) * 4;
#pragma unroll
        for (int i = 0; i < 4; i++) {
            int qq = q4 + i;
            CP16(S0 + QS_OFF + r * 128 + ((qq ^ (r & 7)) << 4), Qg + r * 64 + qq * 8);
        }
    }
    auto load_kv = [&](int jt) {
        uint32_t stK = S0 + KS_OFF + (jt & 1) * 8192;
        uint32_t stV = S0 + VS_OFF + (jt & 1) * 8192;
        int r = t >> 2, q0l = (t & 3) * 2;
        const __half* Kr = Kg + (size_t)(jt * FBN + r) * 64;
        const __half* Vr = Vg + (size_t)(jt * FBN + r) * 64;
#pragma unroll
        for (int i = 0; i < 2; i++) {
            int qq = q0l + i;
            CP16(stK + r * 128 + ((qq ^ (r & 7)) << 4), Kr + qq * 8);
        }
#pragma unroll
        for (int i = 0; i < 2; i++) {
            int qq = q0l + i;
            CP16(stV + r * 128 + ((qq ^ (r & 7)) << 4), Vr + qq * 8);
        }
    };
    load_kv(0); CP_COMMIT();
    load_kv(1); CP_COMMIT();
    CP_WAIT(1);
    __syncthreads();

    // ---- fragment geometry ------------------------------------------------
    const int rx = lane & 7;
    const int r8 = ((lane >> 3) & 1) * 8;
    const int qh = (lane >> 4) & 1;
    const int rB8 = ((lane >> 4) & 1) * 8;
    const int qB  = (lane >> 3) & 1;
    const int g  = lane >> 2, t4 = lane & 3;
    const int row0 = q0 + w * 16 + g;       // this lane's rows: row0, row0+8

    // ---- Q fragments (persistent, 4 k16 steps) ----------------------------
    uint32_t qf[4][4];
    {
        const uint32_t base = S0 + QS_OFF + (w * 16 + r8 + rx) * 128;
#pragma unroll
        for (int ks = 0; ks < 4; ks++)
            ldsm4(qf[ks], base + (((2 * ks + qh) ^ rx) << 4));
    }

    float o[8][4];
#pragma unroll
    for (int nt = 0; nt < 8; nt++)
#pragma unroll
        for (int i = 0; i < 4; i++) o[nt][i] = 0.0f;
    float mrow[2] = { -1e30f, -1e30f };
    float lrow[2] = { 0.0f, 0.0f };

    const float sc = 0.125f;   // 1/sqrt(64)

    for (int jt = 0; jt < ntiles; jt++) {
        if (jt > 0) {
            CP_WAIT(0);
            __syncthreads();
            if (jt + 1 < ntiles) { load_kv(jt + 1); CP_COMMIT(); }
        }
        const int j0 = jt * FBN;
        if (j0 > q0 + w * 16 + 15) continue;   // warp fully masked

        const uint32_t stK = S0 + KS_OFF + (jt & 1) * 8192;
        const uint32_t stV = S0 + VS_OFF + (jt & 1) * 8192;

        // ---- S = Q K^T (k = dk = 64 -> 4 k16 steps) -----------------------
        float s[8][4];
#pragma unroll
        for (int nt = 0; nt < 8; nt++)
#pragma unroll
            for (int i = 0; i < 4; i++) s[nt][i] = 0.0f;

#pragma unroll
        for (int ks = 0; ks < 4; ks++) {
            uint32_t kf[4][4];
            const uint32_t bph = ((2 * ks + qB) ^ rx) << 4;
#pragma unroll
            for (int p = 0; p < 4; p++)
                ldsm4(kf[p], stK + (p * 16 + rB8 + rx) * 128 + bph);
#pragma unroll
            for (int nt = 0; nt < 8; nt++)
                mma_f16(s[nt], qf[ks],
                        kf[nt >> 1][(nt & 1) * 2],
                        kf[nt >> 1][(nt & 1) * 2 + 1]);
        }

        // ---- scale + causal mask + online softmax -------------------------
        const bool full_ok = (j0 + FBN - 1 <= q0 + w * 16);
        float rmax0 = -1e30f, rmax1 = -1e30f;
#pragma unroll
        for (int nt = 0; nt < 8; nt++) {
            const int c0 = j0 + nt * 8 + 2 * t4;
            s[nt][0] *= sc; s[nt][1] *= sc; s[nt][2] *= sc; s[nt][3] *= sc;
            if (!full_ok) {
                if (c0     > row0)     s[nt][0] = -1e30f;
                if (c0 + 1 > row0)     s[nt][1] = -1e30f;
                if (c0     > row0 + 8) s[nt][2] = -1e30f;
                if (c0 + 1 > row0 + 8) s[nt][3] = -1e30f;
            }
            rmax0 = fmaxf(rmax0, fmaxf(s[nt][0], s[nt][1]));
            rmax1 = fmaxf(rmax1, fmaxf(s[nt][2], s[nt][3]));
        }
        rmax0 = fmaxf(rmax0, __shfl_xor_sync(0xffffffffu, rmax0, 1));
        rmax0 = fmaxf(rmax0, __shfl_xor_sync(0xffffffffu, rmax0, 2));
        rmax1 = fmaxf(rmax1, __shfl_xor_sync(0xffffffffu, rmax1, 1));
        rmax1 = fmaxf(rmax1, __shfl_xor_sync(0xffffffffu, rmax1, 2));

        const float mn0 = fmaxf(mrow[0], rmax0);
        const float mn1 = fmaxf(mrow[1], rmax1);
        const float al0 = __expf(mrow[0] - mn0);
        const float al1 = __expf(mrow[1] - mn1);
        float rs0 = 0.0f, rs1 = 0.0f;
#pragma unroll
        for (int nt = 0; nt < 8; nt++) {
            s[nt][0] = __expf(s[nt][0] - mn0);
            s[nt][1] = __expf(s[nt][1] - mn0);
            s[nt][2] = __expf(s[nt][2] - mn1);
            s[nt][3] = __expf(s[nt][3] - mn1);
            rs0 += s[nt][0] + s[nt][1];
            rs1 += s[nt][2] + s[nt][3];
        }
        rs0 += __shfl_xor_sync(0xffffffffu, rs0, 1);
        rs0 += __shfl_xor_sync(0xffffffffu, rs0, 2);
        rs1 += __shfl_xor_sync(0xffffffffu, rs1, 1);
        rs1 += __shfl_xor_sync(0xffffffffu, rs1, 2);
        lrow[0] = lrow[0] * al0 + rs0;  mrow[0] = mn0;
        lrow[1] = lrow[1] * al1 + rs1;  mrow[1] = mn1;
#pragma unroll
        for (int nt = 0; nt < 8; nt++) {
            o[nt][0] *= al0; o[nt][1] *= al0;
            o[nt][2] *= al1; o[nt][3] *= al1;
        }

        // ---- P (fp16) -> smem (per-warp private rows in Q region) ---------
        __syncwarp();
        {
            const int rl = w * 16 + g;
#pragma unroll
            for (int nt = 0; nt < 8; nt++) {
                const uint32_t off = ((nt ^ g) << 4) + 4 * t4;  // quad = nt
                *(__half2*)(sm + QS_OFF + rl * 128 + off) =
                    __floats2half2_rn(s[nt][0], s[nt][1]);
                *(__half2*)(sm + QS_OFF + (rl + 8) * 128 + off) =
                    __floats2half2_rn(s[nt][2], s[nt][3]);
            }
        }
        __syncwarp();

        // ---- O += P V (k = 64 s-positions -> 4 k16 steps) -----------------
        {
            const uint32_t pbase = S0 + QS_OFF + (w * 16 + r8 + rx) * 128;
#pragma unroll
            for (int ks = 0; ks < 4; ks++) {
                uint32_t pf[4];
                ldsm4(pf, pbase + (((2 * ks + qh) ^ rx) << 4));
#pragma unroll
                for (int p = 0; p < 4; p++) {
                    uint32_t vf[4];
                    // trans b-frags: rows = V s-rows (16ks + r8 + rx),
                    // quad = n-tile (2p + qh)
                    ldsm4t(vf, stV + (16 * ks + r8 + rx) * 128 +
                               (((2 * p + qh) ^ rx) << 4));
                    mma_f16(o[2 * p],     pf, vf[0], vf[1]);
                    mma_f16(o[2 * p + 1], pf, vf[2], vf[3]);
                }
            }
        }
        __syncwarp();
    }

    // ---- normalize + write g_oh[token][h*64 + dk] (fp16, producer-rounded)-
    const int b = bh >> 4, h = bh & 15;
    const float inv0 = 1.0f / lrow[0];
    const float inv1 = 1.0f / lrow[1];
#pragma unroll
    for (int nt = 0; nt < 8; nt++) {
        const int col = h * 64 + nt * 8 + 2 * t4;
        *(__half2*)&g_oh[(size_t)(b * SS + row0) * DD + col] =
            __floats2half2_rn(o[nt][0] * inv0, o[nt][1] * inv0);
        *(__half2*)&g_oh[(size_t)(b * SS + row0 + 8) * DD + col] =
            __floats2half2_rn(o[nt][2] * inv1, o[nt][3] * inv1);
    }
}

// ---------------------------------------------------------------------------
extern "C" void kernel_launch(void* const* d_in, const int* in_sizes, int n_in,
                              void* d_out, int out_size)
{
    const float* x      = (const float*)d_in[0];
    // d_in[1] = mask (causal tril; structure exploited directly)
    const float* w_qkv  = (const float*)d_in[2];
    const float* b_qkv  = (const float*)d_in[3];
    const float* w_o    = (const float*)d_in[4];
    const float* b_o    = (const float*)d_in[5];
    float* out          = (float*)d_out;

    (void)in_sizes; (void)n_in; (void)out_size;

    cudaFuncSetAttribute(gemm_mma<0>, cudaFuncAttributeMaxDynamicSharedMemorySize, GEMM_SMEM);
    cudaFuncSetAttribute(gemm_mma<1>, cudaFuncAttributeMaxDynamicSharedMemorySize, GEMM_SMEM);
    cudaFuncSetAttribute(flash_mma_kernel, cudaFuncAttributeMaxDynamicSharedMemorySize, FLASH_SMEM);

    __half2 *d_xh, *d_wqkvh, *d_woh;
    cudaGetSymbolAddress((void**)&d_xh,    g_xh);
    cudaGetSymbolAddress((void**)&d_wqkvh, g_wqkvh);
    cudaGetSymbolAddress((void**)&d_woh,   g_woh);

    // pre-convert all MMA inputs to fp16 (producer-side rounding)
    to_half_kernel<<<NTOK * DD / 1024, 256>>>(x,     d_xh);
    to_half_kernel<<<N3 * DD   / 1024, 256>>>(w_qkv, d_wqkvh);
    to_half_kernel<<<DD * DD   / 1024, 256>>>(w_o,   d_woh);

    dim3 g1(N3 / 128, NTOK / 128);       // 24 x 32
    gemm_mma<0><<<g1, 256, GEMM_SMEM>>>(b_qkv, nullptr);

    dim3 g2(SS / FBM, BB * HH);          // 16 x 32
    flash_mma_kernel<<<g2, 256, FLASH_SMEM>>>();

    dim3 g3(DD / 128, NTOK / 128);       // 8 x 32
    gemm_mma<1><<<g3, 256, GEMM_SMEM>>>(b_o, out);
}

// round 10
// speedup vs baseline: 8.6722x; 1.1355x over previous
#include <cuda_runtime.h>
#include <cuda_fp16.h>
#include <cstdint>

// Problem constants
#define BB   2
#define SS   2048
#define DD   1024
#define HH   16
#define DK   64
#define N3   3072   // 3*D
#define NTOK 4096   // B*S

// Scratch (allocation-free rule: __device__ globals) — all fp16 MMA operands
__device__ __half g_qh[BB * HH * SS * DK];   // [bh, s, dk]
__device__ __half g_kh[BB * HH * SS * DK];
__device__ __half g_vh[BB * HH * SS * DK];
__device__ __half g_oh[NTOK * DD];           // [token, h*64+d]
__device__ __half g_xh[NTOK * DD];           // x -> fp16
__device__ __half g_wqkvh[N3 * DD];          // w_qkv -> fp16
__device__ __half g_woh[DD * DD];            // w_o -> fp16

// ---------------------------------------------------------------------------
// PTX helpers — base sm_80+ ISA only (harness targets plain sm_103: NO tcgen05)
// ---------------------------------------------------------------------------
__device__ __forceinline__ uint32_t smem_u32(const void* p) {
    uint32_t a;
    asm("{ .reg .u64 t; cvta.to.shared.u64 t, %1; cvt.u32.u64 %0, t; }"
        : "=r"(a) : "l"(p));
    return a;
}

#define CP16(dst, src) \
    asm volatile("cp.async.cg.shared.global [%0], [%1], 16;" :: "r"(dst), "l"(src))
#define CP_COMMIT() asm volatile("cp.async.commit_group;" ::: "memory")
#define CP_WAIT(n)  asm volatile("cp.async.wait_group %0;" :: "n"(n) : "memory")

__device__ __forceinline__ void ldsm4(uint32_t* r, uint32_t addr) {
    asm volatile("ldmatrix.sync.aligned.m8n8.x4.shared.b16 {%0,%1,%2,%3}, [%4];"
        : "=r"(r[0]), "=r"(r[1]), "=r"(r[2]), "=r"(r[3]) : "r"(addr));
}
__device__ __forceinline__ void ldsm4t(uint32_t* r, uint32_t addr) {
    asm volatile("ldmatrix.sync.aligned.m8n8.x4.trans.shared.b16 {%0,%1,%2,%3}, [%4];"
        : "=r"(r[0]), "=r"(r[1]), "=r"(r[2]), "=r"(r[3]) : "r"(addr));
}

__device__ __forceinline__ void mma_f16(float* c, const uint32_t* a,
                                        uint32_t b0, uint32_t b1) {
    asm volatile(
        "mma.sync.aligned.m16n8k16.row.col.f32.f16.f16.f32 "
        "{%0,%1,%2,%3}, {%4,%5,%6,%7}, {%8,%9}, {%0,%1,%2,%3};"
        : "+f"(c[0]), "+f"(c[1]), "+f"(c[2]), "+f"(c[3])
        : "r"(a[0]), "r"(a[1]), "r"(a[2]), "r"(a[3]), "r"(b0), "r"(b1));
}

__device__ __forceinline__ float ex2(float x) {
    float r;
    asm("ex2.approx.f32 %0, %1;" : "=f"(r) : "f"(x));
    return r;
}
__device__ __forceinline__ uint32_t pack_h2(float a, float b) {
    __half2 h = __floats2half2_rn(a, b);
    return *(uint32_t*)&h;
}

// ---------------------------------------------------------------------------
// Kernel 0: fused fp32 -> fp16 convert for x, w_qkv, w_o (one launch)
// ---------------------------------------------------------------------------
#define XB  (NTOK * DD / 1024)   // 4096 blocks
#define WB  (N3 * DD / 1024)     // 3072 blocks
#define OB  (DD * DD / 1024)     // 1024 blocks

__global__ __launch_bounds__(256) void to_half_all(
    const float* __restrict__ x, const float* __restrict__ wqkv,
    const float* __restrict__ wo)
{
    int b = blockIdx.x;
    const float* src;  __half2* dst;
    if (b < XB)            { src = x;    dst = (__half2*)g_xh; }
    else if (b < XB + WB)  { src = wqkv; dst = (__half2*)g_wqkvh; b -= XB; }
    else                   { src = wo;   dst = (__half2*)g_woh;   b -= XB + WB; }
    const int i = b * 256 + threadIdx.x;
    float4 v = *(const float4*)(src + i * 4);
    dst[i * 2]     = __floats2half2_rn(v.x, v.y);
    dst[i * 2 + 1] = __floats2half2_rn(v.z, v.w);
}

// ---------------------------------------------------------------------------
// fp16 mma.sync GEMM (proven round-9 version, unchanged)
// ---------------------------------------------------------------------------
#define STAGES      3
#define STAGE_BYTES 32768
#define NCHUNK      16
#define GEMM_SMEM   (1024 + STAGES * STAGE_BYTES)

template<int MODE>
__global__ __launch_bounds__(256, 2) void gemm_mma(
    const float* __restrict__ bias, float* __restrict__ Out)
{
    extern __shared__ __align__(16) char smem_raw[];
    const uint32_t sb  = smem_u32(smem_raw);
    const uint32_t st0 = (sb + 1023u) & ~1023u;

    const int t    = threadIdx.x;
    const int lane = t & 31;
    const int wid  = t >> 5;
    const int wm   = wid & 1;
    const int wn   = wid >> 1;
    const int m0   = blockIdx.y * 128;
    const int n0   = blockIdx.x * 128;

    const __half* A  = (MODE == 1) ? g_oh : g_xh;
    const __half* Bw = (MODE == 1) ? g_woh : g_wqkvh;

    const int rb = t >> 3;
    const int q  = t & 7;
    const __half* Abase = A  + (size_t)m0 * DD + q * 8;
    const __half* Bbase = Bw + (size_t)n0 * DD + q * 8;

    auto load_chunk = [&](int c) {
        const uint32_t st = st0 + (c % STAGES) * STAGE_BYTES;
        const __half* Ac = Abase + c * 64;
        const __half* Bc = Bbase + c * 64;
#pragma unroll
        for (int it = 0; it < 4; it++) {
            int r = rb + it * 32;
            CP16(st + r * 128 + ((q ^ (r & 7)) << 4), Ac + (size_t)r * DD);
        }
#pragma unroll
        for (int it = 0; it < 4; it++) {
            int r = rb + it * 32;
            CP16(st + 16384 + r * 128 + ((q ^ (r & 7)) << 4), Bc + (size_t)r * DD);
        }
    };

    const int rx = lane & 7;
    const int r8 = ((lane >> 3) & 1) * 8;
    const int qh = (lane >> 4) & 1;
    const int rB8 = ((lane >> 4) & 1) * 8;
    const int qB  = (lane >> 3) & 1;

    float acc[4][4][4];
#pragma unroll
    for (int mt = 0; mt < 4; mt++)
#pragma unroll
        for (int nt = 0; nt < 4; nt++)
#pragma unroll
            for (int i = 0; i < 4; i++) acc[mt][nt][i] = 0.0f;

    load_chunk(0); CP_COMMIT();
    load_chunk(1); CP_COMMIT();

    for (int c = 0; c < NCHUNK; c++) {
        CP_WAIT(1);
        __syncthreads();

        if (c + 2 < NCHUNK) load_chunk(c + 2);
        CP_COMMIT();

        const uint32_t stA = st0 + (c % STAGES) * STAGE_BYTES;
        const uint32_t stB = stA + 16384;
#pragma unroll
        for (int ks = 0; ks < 4; ks++) {
            uint32_t a[4][4], b[2][4];
            const uint32_t aph = ((2 * ks + qh) ^ rx) << 4;
            const uint32_t bph = ((2 * ks + qB) ^ rx) << 4;
#pragma unroll
            for (int mt = 0; mt < 4; mt++)
                ldsm4(a[mt], stA + (wm * 64 + mt * 16 + r8 + rx) * 128 + aph);
#pragma unroll
            for (int p = 0; p < 2; p++)
                ldsm4(b[p], stB + (wn * 32 + p * 16 + rB8 + rx) * 128 + bph);
#pragma unroll
            for (int mt = 0; mt < 4; mt++)
#pragma unroll
                for (int nt = 0; nt < 4; nt++)
                    mma_f16(acc[mt][nt], a[mt],
                            b[nt >> 1][(nt & 1) * 2],
                            b[nt >> 1][(nt & 1) * 2 + 1]);
        }
    }

    const int g  = lane >> 2;
    const int t4 = lane & 3;
#pragma unroll
    for (int mt = 0; mt < 4; mt++) {
        const int m = m0 + wm * 64 + mt * 16 + g;
#pragma unroll
        for (int nt = 0; nt < 4; nt++) {
            const int n = n0 + wn * 32 + nt * 8 + 2 * t4;
            const float2 b2 = *(const float2*)&bias[n];
            float2 v0, v1;
            v0.x = acc[mt][nt][0] + b2.x; v0.y = acc[mt][nt][1] + b2.y;
            v1.x = acc[mt][nt][2] + b2.x; v1.y = acc[mt][nt][3] + b2.y;
            if (MODE == 1) {
                *(float2*)&Out[(size_t)m * DD + n]       = v0;
                *(float2*)&Out[(size_t)(m + 8) * DD + n] = v1;
            } else {
                const __half2 h0 = __floats2half2_rn(v0.x, v0.y);
                const __half2 h1 = __floats2half2_rn(v1.x, v1.y);
                const int sel = n >> 10;
                const int h   = (n & 1023) >> 6;
                const int dk  = n & 63;
                __half* dst = (sel == 0) ? g_qh : ((sel == 1) ? g_kh : g_vh);
                const int b0i = m >> 11, s0 = m & 2047;
                *(__half2*)&dst[((size_t)(b0i * HH + h) * SS + s0) * DK + dk] = h0;
                const int b1i = (m + 8) >> 11, s1 = (m + 8) & 2047;
                *(__half2*)&dst[((size_t)(b1i * HH + h) * SS + s1) * DK + dk] = h1;
            }
        }
    }
}

// ---------------------------------------------------------------------------
// Kernel 2: flash attention, fp16 mma.sync, P kept entirely in registers
// (C-frag of S == A-frag of P·V for m16n8k16), exp2-domain softmax.
// BLOCK_M=128, BLOCK_N=64, 8 warps; smem: Q 16KB + K 2x8KB + V 2x8KB = 48KB.
// ---------------------------------------------------------------------------
#define FBM 128
#define FBN 64
#define QS_OFF  0
#define KS_OFF  16384
#define VS_OFF  32768
#define FLASH_SMEM 49152

__global__ __launch_bounds__(256) void flash_mma_kernel()
{
    extern __shared__ __align__(16) char sm[];
    const uint32_t S0 = smem_u32(sm);

    const int t    = threadIdx.x;
    const int lane = t & 31;
    const int w    = t >> 5;
    const int bh   = blockIdx.y;
    const int qt   = (int)gridDim.x - 1 - (int)blockIdx.x;   // heavy first
    const int q0   = qt * FBM;

    const __half* Qg = g_qh + (size_t)(bh * SS + q0) * DK;
    const __half* Kg = g_kh + (size_t)bh * SS * DK;
    const __half* Vg = g_vh + (size_t)bh * SS * DK;

    const int ntiles = q0 / FBN + 2;

    // ---- Q tile -> smem (128 rows x 128B, swizzled) -----------------------
    {
        int r = t >> 1, q4 = (t & 1) * 4;
#pragma unroll
        for (int i = 0; i < 4; i++) {
            int qq = q4 + i;
            CP16(S0 + QS_OFF + r * 128 + ((qq ^ (r & 7)) << 4), Qg + r * 64 + qq * 8);
        }
    }
    auto load_kv = [&](int jt) {
        uint32_t stK = S0 + KS_OFF + (jt & 1) * 8192;
        uint32_t stV = S0 + VS_OFF + (jt & 1) * 8192;
        int r = t >> 2, q0l = (t & 3) * 2;
        const __half* Kr = Kg + (size_t)(jt * FBN + r) * 64;
        const __half* Vr = Vg + (size_t)(jt * FBN + r) * 64;
#pragma unroll
        for (int i = 0; i < 2; i++) {
            int qq = q0l + i;
            CP16(stK + r * 128 + ((qq ^ (r & 7)) << 4), Kr + qq * 8);
        }
#pragma unroll
        for (int i = 0; i < 2; i++) {
            int qq = q0l + i;
            CP16(stV + r * 128 + ((qq ^ (r & 7)) << 4), Vr + qq * 8);
        }
    };
    load_kv(0); CP_COMMIT();
    load_kv(1); CP_COMMIT();
    CP_WAIT(1);
    __syncthreads();

    // ---- fragment geometry ------------------------------------------------
    const int rx = lane & 7;
    const int r8 = ((lane >> 3) & 1) * 8;
    const int qh = (lane >> 4) & 1;
    const int rB8 = ((lane >> 4) & 1) * 8;
    const int qB  = (lane >> 3) & 1;
    const int g  = lane >> 2, t4 = lane & 3;
    const int row0 = q0 + w * 16 + g;       // this lane's rows: row0, row0+8

    // ---- Q fragments (persistent, 4 k16 steps) ----------------------------
    uint32_t qf[4][4];
    {
        const uint32_t base = S0 + QS_OFF + (w * 16 + r8 + rx) * 128;
#pragma unroll
        for (int ks = 0; ks < 4; ks++)
            ldsm4(qf[ks], base + (((2 * ks + qh) ^ rx) << 4));
    }

    float o[8][4];
#pragma unroll
    for (int nt = 0; nt < 8; nt++)
#pragma unroll
        for (int i = 0; i < 4; i++) o[nt][i] = 0.0f;
    float mrow[2] = { -1e30f, -1e30f };     // base-2 domain
    float lrow[2] = { 0.0f, 0.0f };

    const float scL = 0.125f * 1.44269504089f;   // (1/sqrt(64)) * log2(e)

    for (int jt = 0; jt < ntiles; jt++) {
        if (jt > 0) {
            CP_WAIT(0);
            __syncthreads();
            if (jt + 1 < ntiles) { load_kv(jt + 1); CP_COMMIT(); }
        }
        const int j0 = jt * FBN;
        if (j0 > q0 + w * 16 + 15) continue;   // warp fully masked

        const uint32_t stK = S0 + KS_OFF + (jt & 1) * 8192;
        const uint32_t stV = S0 + VS_OFF + (jt & 1) * 8192;

        // ---- S = Q K^T (4 k16 steps) --------------------------------------
        float s[8][4];
#pragma unroll
        for (int nt = 0; nt < 8; nt++)
#pragma unroll
            for (int i = 0; i < 4; i++) s[nt][i] = 0.0f;

#pragma unroll
        for (int ks = 0; ks < 4; ks++) {
            uint32_t kf[4][4];
            const uint32_t bph = ((2 * ks + qB) ^ rx) << 4;
#pragma unroll
            for (int p = 0; p < 4; p++)
                ldsm4(kf[p], stK + (p * 16 + rB8 + rx) * 128 + bph);
#pragma unroll
            for (int nt = 0; nt < 8; nt++)
                mma_f16(s[nt], qf[ks],
                        kf[nt >> 1][(nt & 1) * 2],
                        kf[nt >> 1][(nt & 1) * 2 + 1]);
        }

        // ---- scale (base-2) + causal mask + online softmax ----------------
        const bool full_ok = (j0 + FBN - 1 <= q0 + w * 16);
        float rmax0 = -1e30f, rmax1 = -1e30f;
#pragma unroll
        for (int nt = 0; nt < 8; nt++) {
            const int c0 = j0 + nt * 8 + 2 * t4;
            s[nt][0] *= scL; s[nt][1] *= scL; s[nt][2] *= scL; s[nt][3] *= scL;
            if (!full_ok) {
                if (c0     > row0)     s[nt][0] = -1e30f;
                if (c0 + 1 > row0)     s[nt][1] = -1e30f;
                if (c0     > row0 + 8) s[nt][2] = -1e30f;
                if (c0 + 1 > row0 + 8) s[nt][3] = -1e30f;
            }
            rmax0 = fmaxf(rmax0, fmaxf(s[nt][0], s[nt][1]));
            rmax1 = fmaxf(rmax1, fmaxf(s[nt][2], s[nt][3]));
        }
        rmax0 = fmaxf(rmax0, __shfl_xor_sync(0xffffffffu, rmax0, 1));
        rmax0 = fmaxf(rmax0, __shfl_xor_sync(0xffffffffu, rmax0, 2));
        rmax1 = fmaxf(rmax1, __shfl_xor_sync(0xffffffffu, rmax1, 1));
        rmax1 = fmaxf(rmax1, __shfl_xor_sync(0xffffffffu, rmax1, 2));

        const float mn0 = fmaxf(mrow[0], rmax0);
        const float mn1 = fmaxf(mrow[1], rmax1);
        const float al0 = ex2(mrow[0] - mn0);
        const float al1 = ex2(mrow[1] - mn1);
        float rs0 = 0.0f, rs1 = 0.0f;
#pragma unroll
        for (int nt = 0; nt < 8; nt++) {
            s[nt][0] = ex2(s[nt][0] - mn0);
            s[nt][1] = ex2(s[nt][1] - mn0);
            s[nt][2] = ex2(s[nt][2] - mn1);
            s[nt][3] = ex2(s[nt][3] - mn1);
            rs0 += s[nt][0] + s[nt][1];
            rs1 += s[nt][2] + s[nt][3];
        }
        rs0 += __shfl_xor_sync(0xffffffffu, rs0, 1);
        rs0 += __shfl_xor_sync(0xffffffffu, rs0, 2);
        rs1 += __shfl_xor_sync(0xffffffffu, rs1, 1);
        rs1 += __shfl_xor_sync(0xffffffffu, rs1, 2);
        lrow[0] = lrow[0] * al0 + rs0;  mrow[0] = mn0;
        lrow[1] = lrow[1] * al1 + rs1;  mrow[1] = mn1;
#pragma unroll
        for (int nt = 0; nt < 8; nt++) {
            o[nt][0] *= al0; o[nt][1] *= al0;
            o[nt][2] *= al1; o[nt][3] *= al1;
        }

        // ---- O += P V : P fragments built IN REGISTERS --------------------
        // C-frag (rows g,g+8 ; cols 8nt+2t4,+1) == A-frag layout for k16
        // chunk ks2: {a0,a1,a2,a3} = {(g,klo),(g+8,klo),(g,khi),(g+8,khi)}
#pragma unroll
        for (int ks2 = 0; ks2 < 4; ks2++) {
            uint32_t pf[4];
            pf[0] = pack_h2(s[2 * ks2][0],     s[2 * ks2][1]);
            pf[1] = pack_h2(s[2 * ks2][2],     s[2 * ks2][3]);
            pf[2] = pack_h2(s[2 * ks2 + 1][0], s[2 * ks2 + 1][1]);
            pf[3] = pack_h2(s[2 * ks2 + 1][2], s[2 * ks2 + 1][3]);
#pragma unroll
            for (int p = 0; p < 4; p++) {
                uint32_t vf[4];
                ldsm4t(vf, stV + (16 * ks2 + r8 + rx) * 128 +
                           (((2 * p + qh) ^ rx) << 4));
                mma_f16(o[2 * p],     pf, vf[0], vf[1]);
                mma_f16(o[2 * p + 1], pf, vf[2], vf[3]);
            }
        }
    }

    // ---- normalize + write g_oh[token][h*64 + dk] -------------------------
    const int b = bh >> 4, h = bh & 15;
    const float inv0 = 1.0f / lrow[0];
    const float inv1 = 1.0f / lrow[1];
#pragma unroll
    for (int nt = 0; nt < 8; nt++) {
        const int col = h * 64 + nt * 8 + 2 * t4;
        *(__half2*)&g_oh[(size_t)(b * SS + row0) * DD + col] =
            __floats2half2_rn(o[nt][0] * inv0, o[nt][1] * inv0);
        *(__half2*)&g_oh[(size_t)(b * SS + row0 + 8) * DD + col] =
            __floats2half2_rn(o[nt][2] * inv1, o[nt][3] * inv1);
    }
}

// ---------------------------------------------------------------------------
extern "C" void kernel_launch(void* const* d_in, const int* in_sizes, int n_in,
                              void* d_out, int out_size)
{
    const float* x      = (const float*)d_in[0];
    // d_in[1] = mask (causal tril; structure exploited directly)
    const float* w_qkv  = (const float*)d_in[2];
    const float* b_qkv  = (const float*)d_in[3];
    const float* w_o    = (const float*)d_in[4];
    const float* b_o    = (const float*)d_in[5];
    float* out          = (float*)d_out;

    (void)in_sizes; (void)n_in; (void)out_size;

    cudaFuncSetAttribute(gemm_mma<0>, cudaFuncAttributeMaxDynamicSharedMemorySize, GEMM_SMEM);
    cudaFuncSetAttribute(gemm_mma<1>, cudaFuncAttributeMaxDynamicSharedMemorySize, GEMM_SMEM);
    cudaFuncSetAttribute(flash_mma_kernel, cudaFuncAttributeMaxDynamicSharedMemorySize, FLASH_SMEM);

    // fused pre-convert of all fp32 MMA inputs to fp16
    to_half_all<<<XB + WB + OB, 256>>>(x, w_qkv, w_o);

    dim3 g1(N3 / 128, NTOK / 128);       // 24 x 32
    gemm_mma<0><<<g1, 256, GEMM_SMEM>>>(b_qkv, nullptr);

    dim3 g2(SS / FBM, BB * HH);          // 16 x 32
    flash_mma_kernel<<<g2, 256, FLASH_SMEM>>>();

    dim3 g3(DD / 128, NTOK / 128);       // 8 x 32
    gemm_mma<1><<<g3, 256, GEMM_SMEM>>>(b_o, out);
}